// round 2
// baseline (speedup 1.0000x reference)
#include <cuda_runtime.h>
#include <cuda_bf16.h>
#include <math.h>

// Problem constants
#define PP    2048
#define KK    10
#define LL    3
#define EE    256
#define HH    512
#define G4    2048      // 4*H
#define NPK   20480     // P*K
#define NENT  10000
#define NREL  200

// ---------------- scratch (static device globals; no allocs) ----------------
__device__ float g_W1[G4 * EE];          // w_ih[:, :H] @ kg_proj_w   [2048,256]
__device__ float g_W2[G4 * EE];          // w_ih[:, H:] @ kg_proj_w   [2048,256]
__device__ float g_biasc[G4];            // combined constant gate bias
__device__ float g_rel_gate[NREL * G4];  // rel_table @ W1.T
__device__ float g_ent_gate[NENT * G4];  // ent_table @ W2.T
__device__ float g_h0[NPK * HH];
__device__ float g_h1[NPK * HH];
__device__ float g_c[NPK * HH];
__device__ float g_pemb[NPK * HH];
__device__ float g_qkv[NPK * 3 * HH];
__device__ float g_ctxmean[PP * HH];
__device__ float g_tmp[PP * HH];

__device__ __forceinline__ float sigf(float x) { return 1.0f / (1.0f + expf(-x)); }

// ---------------- generic tiled GEMM: C[M,N] = A[M,K] * op(B) (+bias) -------
// B_TRANS=true : B is [N,K] row-major (C = A @ B^T)
// B_TRANS=false: B is [K,N] row-major (C = A @ B)
#define BM 128
#define BN 64
#define BK 16
#define TPB 256

template <bool B_TRANS, bool BIAS>
__global__ void gemm_kernel(const float* __restrict__ A, const float* __restrict__ B,
                            const float* __restrict__ bias, float* __restrict__ C,
                            int M, int N, int Kd, int lda, int ldb, int ldc) {
    __shared__ float shA[BK][BM + 4];
    __shared__ float shB[BK][BN + 2];
    const int m0 = blockIdx.y * BM;
    const int n0 = blockIdx.x * BN;
    const int tid = threadIdx.x;
    const int jj = tid & 15;     // 0..15
    const int rg = tid >> 4;     // 0..15
    const int r0 = rg * 8;

    float acc[8][4];
#pragma unroll
    for (int i = 0; i < 8; i++)
#pragma unroll
        for (int q = 0; q < 4; q++) acc[i][q] = 0.0f;

    const int a_row = tid >> 2;
    const int a_k4  = (tid & 3) * 4;

    for (int k0 = 0; k0 < Kd; k0 += BK) {
#pragma unroll
        for (int hhalf = 0; hhalf < 2; hhalf++) {
            int r = a_row + hhalf * 64;
            int m = m0 + r;
            float4 v = make_float4(0.f, 0.f, 0.f, 0.f);
            if (m < M) v = *reinterpret_cast<const float4*>(&A[(size_t)m * lda + k0 + a_k4]);
            shA[a_k4 + 0][r] = v.x;
            shA[a_k4 + 1][r] = v.y;
            shA[a_k4 + 2][r] = v.z;
            shA[a_k4 + 3][r] = v.w;
        }
        if (B_TRANS) {
            int c  = tid >> 2;           // 0..63
            int k4 = (tid & 3) * 4;
            float4 v = *reinterpret_cast<const float4*>(&B[(size_t)(n0 + c) * ldb + k0 + k4]);
            shB[k4 + 0][c] = v.x;
            shB[k4 + 1][c] = v.y;
            shB[k4 + 2][c] = v.z;
            shB[k4 + 3][c] = v.w;
        } else {
            int kk2 = tid >> 4;          // 0..15
            int cc  = (tid & 15) * 4;
            float4 v = *reinterpret_cast<const float4*>(&B[(size_t)(k0 + kk2) * ldb + n0 + cc]);
            shB[kk2][cc + 0] = v.x;
            shB[kk2][cc + 1] = v.y;
            shB[kk2][cc + 2] = v.z;
            shB[kk2][cc + 3] = v.w;
        }
        __syncthreads();
#pragma unroll
        for (int k = 0; k < BK; k++) {
            float4 a01 = *reinterpret_cast<const float4*>(&shA[k][r0]);
            float4 a23 = *reinterpret_cast<const float4*>(&shA[k][r0 + 4]);
            float b0 = shB[k][jj], b1 = shB[k][jj + 16], b2 = shB[k][jj + 32], b3 = shB[k][jj + 48];
            float a[8] = {a01.x, a01.y, a01.z, a01.w, a23.x, a23.y, a23.z, a23.w};
#pragma unroll
            for (int i = 0; i < 8; i++) {
                acc[i][0] += a[i] * b0;
                acc[i][1] += a[i] * b1;
                acc[i][2] += a[i] * b2;
                acc[i][3] += a[i] * b3;
            }
        }
        __syncthreads();
    }

    float bv0 = 0.f, bv1 = 0.f, bv2 = 0.f, bv3 = 0.f;
    if (BIAS) {
        bv0 = bias[n0 + jj];
        bv1 = bias[n0 + jj + 16];
        bv2 = bias[n0 + jj + 32];
        bv3 = bias[n0 + jj + 48];
    }
#pragma unroll
    for (int i = 0; i < 8; i++) {
        int m = m0 + r0 + i;
        if (m < M) {
            float* crow = &C[(size_t)m * ldc + n0];
            crow[jj]      = acc[i][0] + bv0;
            crow[jj + 16] = acc[i][1] + bv1;
            crow[jj + 32] = acc[i][2] + bv2;
            crow[jj + 48] = acc[i][3] + bv3;
        }
    }
}

// ---------------- combined gate bias --------------------------------------
// biasc[g] = b_ih[g] + b_hh[g] + sum_h kg_proj_b[h] * (w_ih[g,h] + w_ih[g,H+h])
__global__ void biasc_kernel(const float* __restrict__ kg_proj_b, const float* __restrict__ w_ih,
                             const float* __restrict__ b_ih, const float* __restrict__ b_hh) {
    int g = blockIdx.x;
    float s = 0.f;
    const float* row = &w_ih[(size_t)g * (2 * HH)];
    for (int h = threadIdx.x; h < HH; h += 128) s += kg_proj_b[h] * (row[h] + row[HH + h]);
    __shared__ float red[128];
    red[threadIdx.x] = s;
    __syncthreads();
    for (int off = 64; off > 0; off >>= 1) {
        if (threadIdx.x < off) red[threadIdx.x] += red[threadIdx.x + off];
        __syncthreads();
    }
    if (threadIdx.x == 0) g_biasc[g] = red[0] + b_ih[g] + b_hh[g];
}

// ---------------- LSTM step 0 (h=c=0: gates are pure gathered inputs) ------
__global__ void step0_kernel(const int* __restrict__ rel_idx, const int* __restrict__ ent_idx,
                             const int* __restrict__ path_lens) {
    int n = blockIdx.x;
    int j = threadIdx.x * 4;   // 128 threads * 4 = 512
    int ridx = rel_idx[n * LL + 0];
    int eidx = ent_idx[n * LL + 0];
    int len  = path_lens[n];
    const float* rgp = &g_rel_gate[(size_t)ridx * G4];
    const float* egp = &g_ent_gate[(size_t)eidx * G4];

    float4 h4, c4;
    float* hv = &h4.x;
    float* cv = &c4.x;
#pragma unroll
    for (int u = 0; u < 4; u++) {
        int jc = j + u;
        float gi = rgp[jc]            + egp[jc]            + g_biasc[jc];
        float gg = rgp[2 * HH + jc]   + egp[2 * HH + jc]   + g_biasc[2 * HH + jc];
        float go = rgp[3 * HH + jc]   + egp[3 * HH + jc]   + g_biasc[3 * HH + jc];
        float cn = sigf(gi) * tanhf(gg);
        hv[u] = sigf(go) * tanhf(cn);
        cv[u] = cn;
    }
    size_t off = (size_t)n * HH + j;
    *reinterpret_cast<float4*>(&g_h0[off]) = h4;
    *reinterpret_cast<float4*>(&g_c[off])  = c4;
    if (len == 1) {
        *reinterpret_cast<float4*>(&g_pemb[off]) = h4;
    } else if (len == 0) {
        *reinterpret_cast<float4*>(&g_pemb[off]) = make_float4(0.f, 0.f, 0.f, 0.f);
    }
}

// ---------------- fused LSTM step t (t=1,2): gates = h_prev@w_hh.T + gathers
// Block: 128 rows x 16 hidden cols; micro cols = the 4 gates of one hidden j.
__global__ void lstm_step_kernel(const float* __restrict__ h_prev, float* __restrict__ h_next,
                                 const float* __restrict__ w_hh,
                                 const int* __restrict__ rel_idx, const int* __restrict__ ent_idx,
                                 const int* __restrict__ path_lens, int t) {
    __shared__ float shA[BK][BM + 4];
    __shared__ float shB[BK][BN + 2];
    const int m0 = blockIdx.y * BM;
    const int j0 = blockIdx.x * 16;
    const int tid = threadIdx.x;
    const int jj = tid & 15;
    const int rg = tid >> 4;
    const int r0 = rg * 8;

    float acc[8][4];
#pragma unroll
    for (int i = 0; i < 8; i++)
#pragma unroll
        for (int q = 0; q < 4; q++) acc[i][q] = 0.0f;

    const int a_row = tid >> 2;
    const int a_k4  = (tid & 3) * 4;
    const int b_c   = tid >> 2;                       // tile col 0..63
    const int g_b   = (b_c >> 4) * HH + j0 + (b_c & 15);  // w_hh row (gate*512 + j)
    const int b_k4  = (tid & 3) * 4;

    for (int k0 = 0; k0 < HH; k0 += BK) {
#pragma unroll
        for (int hhalf = 0; hhalf < 2; hhalf++) {
            int r = a_row + hhalf * 64;
            float4 v = *reinterpret_cast<const float4*>(&h_prev[(size_t)(m0 + r) * HH + k0 + a_k4]);
            shA[a_k4 + 0][r] = v.x;
            shA[a_k4 + 1][r] = v.y;
            shA[a_k4 + 2][r] = v.z;
            shA[a_k4 + 3][r] = v.w;
        }
        {
            float4 v = *reinterpret_cast<const float4*>(&w_hh[(size_t)g_b * HH + k0 + b_k4]);
            shB[b_k4 + 0][b_c] = v.x;
            shB[b_k4 + 1][b_c] = v.y;
            shB[b_k4 + 2][b_c] = v.z;
            shB[b_k4 + 3][b_c] = v.w;
        }
        __syncthreads();
#pragma unroll
        for (int k = 0; k < BK; k++) {
            float4 a01 = *reinterpret_cast<const float4*>(&shA[k][r0]);
            float4 a23 = *reinterpret_cast<const float4*>(&shA[k][r0 + 4]);
            float b0 = shB[k][jj], b1 = shB[k][jj + 16], b2 = shB[k][jj + 32], b3 = shB[k][jj + 48];
            float a[8] = {a01.x, a01.y, a01.z, a01.w, a23.x, a23.y, a23.z, a23.w};
#pragma unroll
            for (int i = 0; i < 8; i++) {
                acc[i][0] += a[i] * b0;
                acc[i][1] += a[i] * b1;
                acc[i][2] += a[i] * b2;
                acc[i][3] += a[i] * b3;
            }
        }
        __syncthreads();
    }

    const int j = j0 + jj;
    const float bci = g_biasc[j];
    const float bcf = g_biasc[HH + j];
    const float bcg = g_biasc[2 * HH + j];
    const float bco = g_biasc[3 * HH + j];
#pragma unroll
    for (int i = 0; i < 8; i++) {
        int n = m0 + r0 + i;
        int ridx = rel_idx[n * LL + t];
        int eidx = ent_idx[n * LL + t];
        const float* rgp = &g_rel_gate[(size_t)ridx * G4];
        const float* egp = &g_ent_gate[(size_t)eidx * G4];
        float gi = acc[i][0] + rgp[j]           + egp[j]           + bci;
        float gf = acc[i][1] + rgp[HH + j]      + egp[HH + j]      + bcf;
        float gg = acc[i][2] + rgp[2 * HH + j]  + egp[2 * HH + j]  + bcg;
        float go = acc[i][3] + rgp[3 * HH + j]  + egp[3 * HH + j]  + bco;
        size_t off = (size_t)n * HH + j;
        float cn = sigf(gf) * g_c[off] + sigf(gi) * tanhf(gg);
        float hn = sigf(go) * tanhf(cn);
        g_c[off] = cn;
        h_next[off] = hn;
        if (path_lens[n] == t + 1) g_pemb[off] = hn;
    }
}

// ---------------- per-pair attention; mean over K folded into column-sum ----
__global__ void attn_kernel() {
    int p = blockIdx.x;
    int tid = threadIdx.x;  // 256
    __shared__ float sq[KK][128], sk[KK][128], sv[KK][128];
    __shared__ float sc[KK][KK + 2];
    __shared__ float wcol[KK];

    for (int hd = 0; hd < 4; hd++) {
        for (int i = tid; i < KK * 128; i += 256) {
            int a = i >> 7, d = i & 127;
            size_t base = (size_t)(p * KK + a) * (3 * HH) + hd * 128 + d;
            sq[a][d] = g_qkv[base];
            sk[a][d] = g_qkv[base + HH];
            sv[a][d] = g_qkv[base + 2 * HH];
        }
        __syncthreads();
        if (tid < KK * KK) {
            int a = tid / KK, b = tid % KK;
            float s = 0.f;
#pragma unroll 8
            for (int d = 0; d < 128; d++) s += sq[a][d] * sk[b][d];
            sc[a][b] = s * 0.08838834764831845f;  // 1/sqrt(128)
        }
        __syncthreads();
        if (tid < KK) {
            int a = tid;
            float mx = -1e30f;
            for (int b = 0; b < KK; b++) mx = fmaxf(mx, sc[a][b]);
            float e[KK], sum = 0.f;
            for (int b = 0; b < KK; b++) { e[b] = expf(sc[a][b] - mx); sum += e[b]; }
            float inv = 1.f / sum;
            for (int b = 0; b < KK; b++) sc[a][b] = e[b] * inv;
        }
        __syncthreads();
        if (tid < KK) {
            int b = tid;
            float s = 0.f;
            for (int a = 0; a < KK; a++) s += sc[a][b];
            wcol[b] = s * 0.1f;  // mean over K queries
        }
        __syncthreads();
        if (tid < 128) {
            int d = tid;
            float s = 0.f;
#pragma unroll
            for (int b = 0; b < KK; b++) s += wcol[b] * sv[b][d];
            g_ctxmean[(size_t)p * HH + hd * 128 + d] = s;
        }
        __syncthreads();
    }
}

// ---------------- launch --------------------------------------------------
extern "C" void kernel_launch(void* const* d_in, const int* in_sizes, int n_in,
                              void* d_out, int out_size) {
    const int*   rel_idx     = (const int*)d_in[0];
    const int*   ent_idx     = (const int*)d_in[1];
    const int*   path_lens   = (const int*)d_in[2];
    const float* rel_table   = (const float*)d_in[3];
    const float* ent_table   = (const float*)d_in[4];
    const float* kg_proj_w   = (const float*)d_in[5];
    const float* kg_proj_b   = (const float*)d_in[6];
    const float* w_ih        = (const float*)d_in[7];
    const float* w_hh        = (const float*)d_in[8];
    const float* b_ih        = (const float*)d_in[9];
    const float* b_hh        = (const float*)d_in[10];
    const float* attn_in_w   = (const float*)d_in[11];
    const float* attn_in_b   = (const float*)d_in[12];
    const float* attn_out_w  = (const float*)d_in[13];
    const float* attn_out_b  = (const float*)d_in[14];
    const float* path_proj_w = (const float*)d_in[15];
    const float* path_proj_b = (const float*)d_in[16];
    float* out = (float*)d_out;

    float *pW1, *pW2, *pRel, *pEnt, *pH0, *pH1, *pPemb, *pQkv, *pCtx, *pTmp;
    cudaGetSymbolAddress((void**)&pW1, g_W1);
    cudaGetSymbolAddress((void**)&pW2, g_W2);
    cudaGetSymbolAddress((void**)&pRel, g_rel_gate);
    cudaGetSymbolAddress((void**)&pEnt, g_ent_gate);
    cudaGetSymbolAddress((void**)&pH0, g_h0);
    cudaGetSymbolAddress((void**)&pH1, g_h1);
    cudaGetSymbolAddress((void**)&pPemb, g_pemb);
    cudaGetSymbolAddress((void**)&pQkv, g_qkv);
    cudaGetSymbolAddress((void**)&pCtx, g_ctxmean);
    cudaGetSymbolAddress((void**)&pTmp, g_tmp);

    // 1. folded weights: W1 = w_ih[:, :H] @ kg_proj_w ; W2 = w_ih[:, H:] @ kg_proj_w
    {
        dim3 grid(EE / BN, G4 / BM);  // (4, 16)
        gemm_kernel<false, false><<<grid, TPB>>>(w_ih,      kg_proj_w, nullptr, pW1,
                                                 G4, EE, HH, 2 * HH, EE, EE);
        gemm_kernel<false, false><<<grid, TPB>>>(w_ih + HH, kg_proj_w, nullptr, pW2,
                                                 G4, EE, HH, 2 * HH, EE, EE);
    }
    biasc_kernel<<<G4, 128>>>(kg_proj_b, w_ih, b_ih, b_hh);

    // 2. per-entity gate tables
    gemm_kernel<true, false><<<dim3(G4 / BN, (NENT + BM - 1) / BM), TPB>>>(
        ent_table, pW2, nullptr, pEnt, NENT, G4, EE, EE, EE, G4);
    gemm_kernel<true, false><<<dim3(G4 / BN, (NREL + BM - 1) / BM), TPB>>>(
        rel_table, pW1, nullptr, pRel, NREL, G4, EE, EE, EE, G4);

    // 3. LSTM: step 0 (pure gather), steps 1 & 2 (fused GEMM + cell)
    step0_kernel<<<NPK, 128>>>(rel_idx, ent_idx, path_lens);
    lstm_step_kernel<<<dim3(HH / 16, NPK / BM), TPB>>>(pH0, pH1, w_hh, rel_idx, ent_idx, path_lens, 1);
    lstm_step_kernel<<<dim3(HH / 16, NPK / BM), TPB>>>(pH1, pH0, w_hh, rel_idx, ent_idx, path_lens, 2);

    // 4. QKV projection
    gemm_kernel<true, true><<<dim3(3 * HH / BN, NPK / BM), TPB>>>(
        pPemb, attn_in_w, attn_in_b, pQkv, NPK, 3 * HH, HH, HH, HH, 3 * HH);

    // 5. attention with folded mean
    attn_kernel<<<PP, 256>>>();

    // 6. final projections: (ctx_mean @ attn_out_w.T + b) @ path_proj_w.T + b
    gemm_kernel<true, true><<<dim3(HH / BN, PP / BM), TPB>>>(
        pCtx, attn_out_w, attn_out_b, pTmp, PP, HH, HH, HH, HH, HH);
    gemm_kernel<true, true><<<dim3(HH / BN, PP / BM), TPB>>>(
        pTmp, path_proj_w, path_proj_b, out, PP, HH, HH, HH, HH, HH);
}

// round 3
// speedup vs baseline: 1.6814x; 1.6814x over previous
#include <cuda_runtime.h>
#include <cuda_bf16.h>
#include <math.h>

// Problem constants
#define PP    2048
#define KK    10
#define LL    3
#define EE    256
#define HH    512
#define G4    2048      // 4*H
#define NPK   20480     // P*K
#define NENT  10000
#define NREL  200

// ---------------- scratch (static device globals; no allocs) ----------------
__device__ float g_W1[G4 * EE];          // w_ih[:, :H] @ kg_proj_w   [2048,256]
__device__ float g_W2[G4 * EE];          // w_ih[:, H:] @ kg_proj_w   [2048,256]
__device__ float g_biasc[G4];            // combined constant gate bias
__device__ float g_rel_gate[NREL * G4];  // rel_table @ W1.T
__device__ float g_ent_gate[NENT * G4];  // ent_table @ W2.T
__device__ float g_h0[NPK * HH];         // permuted layout
__device__ float g_h1[NPK * HH];         // permuted layout
__device__ float g_c[NPK * HH];          // permuted layout
__device__ float g_pemb[NPK * HH];       // ORIGINAL layout
__device__ float g_qkv[NPK * 3 * HH];    // ORIGINAL layout
__device__ float g_ctxmean[PP * HH];
__device__ float g_tmp[PP * HH];

// length-sort state
__device__ int g_bins[4];
__device__ int g_off[4];
__device__ int g_cnt[3];                 // [0]=#len3, [1]=#len>=2, [2]=#len>=1
__device__ int g_perm[NPK];              // permuted -> original row

__device__ __forceinline__ float sigf(float x) { return 1.0f / (1.0f + expf(-x)); }

#define BM 128
#define BN 64
#define BK 16
#define TPB 256

// ---------------- generic tiled GEMM: C[M,N] = A[M,K] * op(B) (+bias) -------
template <bool B_TRANS, bool BIAS>
__global__ void gemm_kernel(const float* __restrict__ A, const float* __restrict__ B,
                            const float* __restrict__ bias, float* __restrict__ C,
                            int M, int N, int Kd, int lda, int ldb, int ldc) {
    __shared__ float shA[BK][BM + 4];
    __shared__ float shB[BK][BN + 2];
    const int m0 = blockIdx.y * BM;
    const int n0 = blockIdx.x * BN;
    const int tid = threadIdx.x;
    const int jj = tid & 15;
    const int rg = tid >> 4;
    const int r0 = rg * 8;

    float acc[8][4];
#pragma unroll
    for (int i = 0; i < 8; i++)
#pragma unroll
        for (int q = 0; q < 4; q++) acc[i][q] = 0.0f;

    const int a_row = tid >> 2;
    const int a_k4  = (tid & 3) * 4;

    for (int k0 = 0; k0 < Kd; k0 += BK) {
#pragma unroll
        for (int hhalf = 0; hhalf < 2; hhalf++) {
            int r = a_row + hhalf * 64;
            int m = m0 + r;
            float4 v = make_float4(0.f, 0.f, 0.f, 0.f);
            if (m < M) v = *reinterpret_cast<const float4*>(&A[(size_t)m * lda + k0 + a_k4]);
            shA[a_k4 + 0][r] = v.x;
            shA[a_k4 + 1][r] = v.y;
            shA[a_k4 + 2][r] = v.z;
            shA[a_k4 + 3][r] = v.w;
        }
        if (B_TRANS) {
            int c  = tid >> 2;
            int k4 = (tid & 3) * 4;
            float4 v = *reinterpret_cast<const float4*>(&B[(size_t)(n0 + c) * ldb + k0 + k4]);
            shB[k4 + 0][c] = v.x;
            shB[k4 + 1][c] = v.y;
            shB[k4 + 2][c] = v.z;
            shB[k4 + 3][c] = v.w;
        } else {
            int kk2 = tid >> 4;
            int cc  = (tid & 15) * 4;
            float4 v = *reinterpret_cast<const float4*>(&B[(size_t)(k0 + kk2) * ldb + n0 + cc]);
            shB[kk2][cc + 0] = v.x;
            shB[kk2][cc + 1] = v.y;
            shB[kk2][cc + 2] = v.z;
            shB[kk2][cc + 3] = v.w;
        }
        __syncthreads();
#pragma unroll
        for (int k = 0; k < BK; k++) {
            float4 a01 = *reinterpret_cast<const float4*>(&shA[k][r0]);
            float4 a23 = *reinterpret_cast<const float4*>(&shA[k][r0 + 4]);
            float b0 = shB[k][jj], b1 = shB[k][jj + 16], b2 = shB[k][jj + 32], b3 = shB[k][jj + 48];
            float a[8] = {a01.x, a01.y, a01.z, a01.w, a23.x, a23.y, a23.z, a23.w};
#pragma unroll
            for (int i = 0; i < 8; i++) {
                acc[i][0] += a[i] * b0;
                acc[i][1] += a[i] * b1;
                acc[i][2] += a[i] * b2;
                acc[i][3] += a[i] * b3;
            }
        }
        __syncthreads();
    }

    float bv0 = 0.f, bv1 = 0.f, bv2 = 0.f, bv3 = 0.f;
    if (BIAS) {
        bv0 = bias[n0 + jj];
        bv1 = bias[n0 + jj + 16];
        bv2 = bias[n0 + jj + 32];
        bv3 = bias[n0 + jj + 48];
    }
#pragma unroll
    for (int i = 0; i < 8; i++) {
        int m = m0 + r0 + i;
        if (m < M) {
            float* crow = &C[(size_t)m * ldc + n0];
            crow[jj]      = acc[i][0] + bv0;
            crow[jj + 16] = acc[i][1] + bv1;
            crow[jj + 32] = acc[i][2] + bv2;
            crow[jj + 48] = acc[i][3] + bv3;
        }
    }
}

// ---------------- combined gate bias --------------------------------------
__global__ void biasc_kernel(const float* __restrict__ kg_proj_b, const float* __restrict__ w_ih,
                             const float* __restrict__ b_ih, const float* __restrict__ b_hh) {
    int g = blockIdx.x;
    float s = 0.f;
    const float* row = &w_ih[(size_t)g * (2 * HH)];
    for (int h = threadIdx.x; h < HH; h += 128) s += kg_proj_b[h] * (row[h] + row[HH + h]);
    __shared__ float red[128];
    red[threadIdx.x] = s;
    __syncthreads();
    for (int off = 64; off > 0; off >>= 1) {
        if (threadIdx.x < off) red[threadIdx.x] += red[threadIdx.x + off];
        __syncthreads();
    }
    if (threadIdx.x == 0) g_biasc[g] = red[0] + b_ih[g] + b_hh[g];
}

// ---------------- counting sort by path length (descending) ----------------
__global__ void sort_init() {
    if (threadIdx.x < 4) g_bins[threadIdx.x] = 0;
}
__global__ void sort_count(const int* __restrict__ lens) {
    int n = blockIdx.x * blockDim.x + threadIdx.x;
    if (n < NPK) {
        int l = lens[n]; l = max(0, min(3, l));
        atomicAdd(&g_bins[3 - l], 1);
    }
}
__global__ void sort_prefix() {
    int c0 = g_bins[0], c1 = g_bins[1], c2 = g_bins[2];
    g_off[0] = 0; g_off[1] = c0; g_off[2] = c0 + c1; g_off[3] = c0 + c1 + c2;
    g_cnt[0] = c0; g_cnt[1] = c0 + c1; g_cnt[2] = c0 + c1 + c2;
}
__global__ void sort_scatter(const int* __restrict__ lens) {
    int n = blockIdx.x * blockDim.x + threadIdx.x;
    if (n < NPK) {
        int l = lens[n]; l = max(0, min(3, l));
        int pos = atomicAdd(&g_off[3 - l], 1);
        g_perm[pos] = n;
    }
}

// ---------------- LSTM step 0 (h=c=0), permuted layout ---------------------
__global__ void step0_kernel(const int* __restrict__ rel_idx, const int* __restrict__ ent_idx,
                             const int* __restrict__ path_lens, const int* __restrict__ perm) {
    int n = blockIdx.x;                 // permuted row
    int orig = perm[n];
    int j = threadIdx.x * 4;
    int ridx = rel_idx[orig * LL + 0];
    int eidx = ent_idx[orig * LL + 0];
    int len  = path_lens[orig];
    const float* rgp = &g_rel_gate[(size_t)ridx * G4];
    const float* egp = &g_ent_gate[(size_t)eidx * G4];

    float4 h4, c4;
    float* hv = &h4.x;
    float* cv = &c4.x;
#pragma unroll
    for (int u = 0; u < 4; u++) {
        int jc = j + u;
        float gi = rgp[jc]          + egp[jc]          + g_biasc[jc];
        float gg = rgp[2 * HH + jc] + egp[2 * HH + jc] + g_biasc[2 * HH + jc];
        float go = rgp[3 * HH + jc] + egp[3 * HH + jc] + g_biasc[3 * HH + jc];
        float cn = sigf(gi) * tanhf(gg);
        hv[u] = sigf(go) * tanhf(cn);
        cv[u] = cn;
    }
    size_t offp = (size_t)n * HH + j;
    *reinterpret_cast<float4*>(&g_h0[offp]) = h4;
    *reinterpret_cast<float4*>(&g_c[offp])  = c4;
    size_t offo = (size_t)orig * HH + j;
    if (len == 1) {
        *reinterpret_cast<float4*>(&g_pemb[offo]) = h4;
    } else if (len == 0) {
        *reinterpret_cast<float4*>(&g_pemb[offo]) = make_float4(0.f, 0.f, 0.f, 0.f);
    }
}

// ---------------- fused LSTM step t (t=1,2) on compacted prefix ------------
__global__ void lstm_step_kernel(const float* __restrict__ h_prev, float* __restrict__ h_next,
                                 const float* __restrict__ w_hh,
                                 const int* __restrict__ rel_idx, const int* __restrict__ ent_idx,
                                 const int* __restrict__ path_lens, int t,
                                 const int* __restrict__ perm, const int* __restrict__ cntp) {
    const int m0 = blockIdx.y * BM;
    const int cnt = __ldg(cntp);
    if (m0 >= cnt) return;

    __shared__ float shA[BK][BM + 4];
    __shared__ float shB[BK][BN + 2];
    const int j0 = blockIdx.x * 16;
    const int tid = threadIdx.x;
    const int jj = tid & 15;
    const int rg = tid >> 4;
    const int r0 = rg * 8;

    float acc[8][4];
#pragma unroll
    for (int i = 0; i < 8; i++)
#pragma unroll
        for (int q = 0; q < 4; q++) acc[i][q] = 0.0f;

    const int a_row = tid >> 2;
    const int a_k4  = (tid & 3) * 4;
    const int b_c   = tid >> 2;
    const int g_b   = (b_c >> 4) * HH + j0 + (b_c & 15);
    const int b_k4  = (tid & 3) * 4;

    for (int k0 = 0; k0 < HH; k0 += BK) {
#pragma unroll
        for (int hhalf = 0; hhalf < 2; hhalf++) {
            int r = a_row + hhalf * 64;
            float4 v = *reinterpret_cast<const float4*>(&h_prev[(size_t)(m0 + r) * HH + k0 + a_k4]);
            shA[a_k4 + 0][r] = v.x;
            shA[a_k4 + 1][r] = v.y;
            shA[a_k4 + 2][r] = v.z;
            shA[a_k4 + 3][r] = v.w;
        }
        {
            float4 v = *reinterpret_cast<const float4*>(&w_hh[(size_t)g_b * HH + k0 + b_k4]);
            shB[b_k4 + 0][b_c] = v.x;
            shB[b_k4 + 1][b_c] = v.y;
            shB[b_k4 + 2][b_c] = v.z;
            shB[b_k4 + 3][b_c] = v.w;
        }
        __syncthreads();
#pragma unroll
        for (int k = 0; k < BK; k++) {
            float4 a01 = *reinterpret_cast<const float4*>(&shA[k][r0]);
            float4 a23 = *reinterpret_cast<const float4*>(&shA[k][r0 + 4]);
            float b0 = shB[k][jj], b1 = shB[k][jj + 16], b2 = shB[k][jj + 32], b3 = shB[k][jj + 48];
            float a[8] = {a01.x, a01.y, a01.z, a01.w, a23.x, a23.y, a23.z, a23.w};
#pragma unroll
            for (int i = 0; i < 8; i++) {
                acc[i][0] += a[i] * b0;
                acc[i][1] += a[i] * b1;
                acc[i][2] += a[i] * b2;
                acc[i][3] += a[i] * b3;
            }
        }
        __syncthreads();
    }

    const int j = j0 + jj;
    const float bci = g_biasc[j];
    const float bcf = g_biasc[HH + j];
    const float bcg = g_biasc[2 * HH + j];
    const float bco = g_biasc[3 * HH + j];
#pragma unroll
    for (int i = 0; i < 8; i++) {
        int n = m0 + r0 + i;            // permuted row
        int orig = perm[n];
        int ridx = rel_idx[orig * LL + t];
        int eidx = ent_idx[orig * LL + t];
        const float* rgp = &g_rel_gate[(size_t)ridx * G4];
        const float* egp = &g_ent_gate[(size_t)eidx * G4];
        float gi = acc[i][0] + rgp[j]          + egp[j]          + bci;
        float gf = acc[i][1] + rgp[HH + j]     + egp[HH + j]     + bcf;
        float gg = acc[i][2] + rgp[2 * HH + j] + egp[2 * HH + j] + bcg;
        float go = acc[i][3] + rgp[3 * HH + j] + egp[3 * HH + j] + bco;
        size_t offp = (size_t)n * HH + j;
        float cn = sigf(gf) * g_c[offp] + sigf(gi) * tanhf(gg);
        float hn = sigf(go) * tanhf(cn);
        g_c[offp] = cn;
        h_next[offp] = hn;
        if (path_lens[orig] == t + 1) g_pemb[(size_t)orig * HH + j] = hn;
    }
}

// ---------------- QKV GEMM with row-gather through perm (len>0 prefix) -----
__global__ void qkv_gemm_kernel(const float* __restrict__ A /*pemb, orig layout*/,
                                const float* __restrict__ B /*attn_in_w [3H,H]*/,
                                const float* __restrict__ bias, float* __restrict__ C,
                                const int* __restrict__ perm, const int* __restrict__ cntp) {
    const int m0 = blockIdx.y * BM;
    const int cnt = __ldg(cntp);
    if (m0 >= cnt) return;

    __shared__ float shA[BK][BM + 4];
    __shared__ float shB[BK][BN + 2];
    __shared__ int sPerm[BM];
    const int n0 = blockIdx.x * BN;
    const int tid = threadIdx.x;
    const int jj = tid & 15;
    const int rg = tid >> 4;
    const int r0 = rg * 8;

    if (tid < BM) sPerm[tid] = perm[m0 + tid];
    __syncthreads();

    float acc[8][4];
#pragma unroll
    for (int i = 0; i < 8; i++)
#pragma unroll
        for (int q = 0; q < 4; q++) acc[i][q] = 0.0f;

    const int a_row = tid >> 2;
    const int a_k4  = (tid & 3) * 4;

    for (int k0 = 0; k0 < HH; k0 += BK) {
#pragma unroll
        for (int hhalf = 0; hhalf < 2; hhalf++) {
            int r = a_row + hhalf * 64;
            int m = sPerm[r];
            float4 v = *reinterpret_cast<const float4*>(&A[(size_t)m * HH + k0 + a_k4]);
            shA[a_k4 + 0][r] = v.x;
            shA[a_k4 + 1][r] = v.y;
            shA[a_k4 + 2][r] = v.z;
            shA[a_k4 + 3][r] = v.w;
        }
        {
            int c  = tid >> 2;
            int k4 = (tid & 3) * 4;
            float4 v = *reinterpret_cast<const float4*>(&B[(size_t)(n0 + c) * HH + k0 + k4]);
            shB[k4 + 0][c] = v.x;
            shB[k4 + 1][c] = v.y;
            shB[k4 + 2][c] = v.z;
            shB[k4 + 3][c] = v.w;
        }
        __syncthreads();
#pragma unroll
        for (int k = 0; k < BK; k++) {
            float4 a01 = *reinterpret_cast<const float4*>(&shA[k][r0]);
            float4 a23 = *reinterpret_cast<const float4*>(&shA[k][r0 + 4]);
            float b0 = shB[k][jj], b1 = shB[k][jj + 16], b2 = shB[k][jj + 32], b3 = shB[k][jj + 48];
            float a[8] = {a01.x, a01.y, a01.z, a01.w, a23.x, a23.y, a23.z, a23.w};
#pragma unroll
            for (int i = 0; i < 8; i++) {
                acc[i][0] += a[i] * b0;
                acc[i][1] += a[i] * b1;
                acc[i][2] += a[i] * b2;
                acc[i][3] += a[i] * b3;
            }
        }
        __syncthreads();
    }

    const float bv0 = bias[n0 + jj];
    const float bv1 = bias[n0 + jj + 16];
    const float bv2 = bias[n0 + jj + 32];
    const float bv3 = bias[n0 + jj + 48];
#pragma unroll
    for (int i = 0; i < 8; i++) {
        int orig = sPerm[r0 + i];
        float* crow = &C[(size_t)orig * (3 * HH) + n0];
        crow[jj]      = acc[i][0] + bv0;
        crow[jj + 16] = acc[i][1] + bv1;
        crow[jj + 32] = acc[i][2] + bv2;
        crow[jj + 48] = acc[i][3] + bv3;
    }
}

// qkv rows for len==0 paths: pemb row is zero -> qkv row = bias
__global__ void qkv_fill_kernel(const float* __restrict__ bias,
                                const int* __restrict__ perm, const int* __restrict__ cntp) {
    int m = blockIdx.x;
    if (m < __ldg(cntp)) return;
    int orig = perm[m];
    float4* row = reinterpret_cast<float4*>(&g_qkv[(size_t)orig * (3 * HH)]);
    const float4* b4 = reinterpret_cast<const float4*>(bias);
    for (int i = threadIdx.x; i < (3 * HH) / 4; i += blockDim.x) row[i] = b4[i];
}

// ---------------- per-pair attention; mean over K folded into column-sum ----
__global__ void attn_kernel() {
    int p = blockIdx.x;
    int tid = threadIdx.x;
    __shared__ float sq[KK][128], sk[KK][128], sv[KK][128];
    __shared__ float sc[KK][KK + 2];
    __shared__ float wcol[KK];

    for (int hd = 0; hd < 4; hd++) {
        for (int i = tid; i < KK * 128; i += 256) {
            int a = i >> 7, d = i & 127;
            size_t base = (size_t)(p * KK + a) * (3 * HH) + hd * 128 + d;
            sq[a][d] = g_qkv[base];
            sk[a][d] = g_qkv[base + HH];
            sv[a][d] = g_qkv[base + 2 * HH];
        }
        __syncthreads();
        if (tid < KK * KK) {
            int a = tid / KK, b = tid % KK;
            float s = 0.f;
#pragma unroll 8
            for (int d = 0; d < 128; d++) s += sq[a][d] * sk[b][d];
            sc[a][b] = s * 0.08838834764831845f;
        }
        __syncthreads();
        if (tid < KK) {
            int a = tid;
            float mx = -1e30f;
            for (int b = 0; b < KK; b++) mx = fmaxf(mx, sc[a][b]);
            float e[KK], sum = 0.f;
            for (int b = 0; b < KK; b++) { e[b] = expf(sc[a][b] - mx); sum += e[b]; }
            float inv = 1.f / sum;
            for (int b = 0; b < KK; b++) sc[a][b] = e[b] * inv;
        }
        __syncthreads();
        if (tid < KK) {
            int b = tid;
            float s = 0.f;
            for (int a = 0; a < KK; a++) s += sc[a][b];
            wcol[b] = s * 0.1f;
        }
        __syncthreads();
        if (tid < 128) {
            int d = tid;
            float s = 0.f;
#pragma unroll
            for (int b = 0; b < KK; b++) s += wcol[b] * sv[b][d];
            g_ctxmean[(size_t)p * HH + hd * 128 + d] = s;
        }
        __syncthreads();
    }
}

// ---------------- launch --------------------------------------------------
extern "C" void kernel_launch(void* const* d_in, const int* in_sizes, int n_in,
                              void* d_out, int out_size) {
    const int*   rel_idx     = (const int*)d_in[0];
    const int*   ent_idx     = (const int*)d_in[1];
    const int*   path_lens   = (const int*)d_in[2];
    const float* rel_table   = (const float*)d_in[3];
    const float* ent_table   = (const float*)d_in[4];
    const float* kg_proj_w   = (const float*)d_in[5];
    const float* kg_proj_b   = (const float*)d_in[6];
    const float* w_ih        = (const float*)d_in[7];
    const float* w_hh        = (const float*)d_in[8];
    const float* b_ih        = (const float*)d_in[9];
    const float* b_hh        = (const float*)d_in[10];
    const float* attn_in_w   = (const float*)d_in[11];
    const float* attn_in_b   = (const float*)d_in[12];
    const float* attn_out_w  = (const float*)d_in[13];
    const float* attn_out_b  = (const float*)d_in[14];
    const float* path_proj_w = (const float*)d_in[15];
    const float* path_proj_b = (const float*)d_in[16];
    float* out = (float*)d_out;

    float *pW1, *pW2, *pRel, *pEnt, *pH0, *pH1, *pPemb, *pQkv, *pCtx, *pTmp;
    int *pPerm, *pCnt;
    cudaGetSymbolAddress((void**)&pW1, g_W1);
    cudaGetSymbolAddress((void**)&pW2, g_W2);
    cudaGetSymbolAddress((void**)&pRel, g_rel_gate);
    cudaGetSymbolAddress((void**)&pEnt, g_ent_gate);
    cudaGetSymbolAddress((void**)&pH0, g_h0);
    cudaGetSymbolAddress((void**)&pH1, g_h1);
    cudaGetSymbolAddress((void**)&pPemb, g_pemb);
    cudaGetSymbolAddress((void**)&pQkv, g_qkv);
    cudaGetSymbolAddress((void**)&pCtx, g_ctxmean);
    cudaGetSymbolAddress((void**)&pTmp, g_tmp);
    cudaGetSymbolAddress((void**)&pPerm, g_perm);
    cudaGetSymbolAddress((void**)&pCnt, g_cnt);

    // 0. counting sort by path length (descending)
    sort_init<<<1, 32>>>();
    sort_count<<<(NPK + 255) / 256, 256>>>(path_lens);
    sort_prefix<<<1, 1>>>();
    sort_scatter<<<(NPK + 255) / 256, 256>>>(path_lens);

    // 1. folded weights: W1 = w_ih[:, :H] @ kg_proj_w ; W2 = w_ih[:, H:] @ kg_proj_w
    {
        dim3 grid(EE / BN, G4 / BM);
        gemm_kernel<false, false><<<grid, TPB>>>(w_ih,      kg_proj_w, nullptr, pW1,
                                                 G4, EE, HH, 2 * HH, EE, EE);
        gemm_kernel<false, false><<<grid, TPB>>>(w_ih + HH, kg_proj_w, nullptr, pW2,
                                                 G4, EE, HH, 2 * HH, EE, EE);
    }
    biasc_kernel<<<G4, 128>>>(kg_proj_b, w_ih, b_ih, b_hh);

    // 2. per-entity gate tables
    gemm_kernel<true, false><<<dim3(G4 / BN, (NENT + BM - 1) / BM), TPB>>>(
        ent_table, pW2, nullptr, pEnt, NENT, G4, EE, EE, EE, G4);
    gemm_kernel<true, false><<<dim3(G4 / BN, (NREL + BM - 1) / BM), TPB>>>(
        rel_table, pW1, nullptr, pRel, NREL, G4, EE, EE, EE, G4);

    // 3. LSTM: step 0 on all rows (permuted layout); steps 1,2 on compacted prefix
    step0_kernel<<<NPK, 128>>>(rel_idx, ent_idx, path_lens, pPerm);
    lstm_step_kernel<<<dim3(HH / 16, NPK / BM), TPB>>>(pH0, pH1, w_hh, rel_idx, ent_idx,
                                                       path_lens, 1, pPerm, pCnt + 1);
    lstm_step_kernel<<<dim3(HH / 16, NPK / BM), TPB>>>(pH1, pH0, w_hh, rel_idx, ent_idx,
                                                       path_lens, 2, pPerm, pCnt + 0);

    // 4. QKV: GEMM on len>0 rows (gathered), bias-fill for len==0 rows
    qkv_gemm_kernel<<<dim3(3 * HH / BN, NPK / BM), TPB>>>(
        pPemb, attn_in_w, attn_in_b, pQkv, pPerm, pCnt + 2);
    qkv_fill_kernel<<<NPK, 128>>>(attn_in_b, pPerm, pCnt + 2);

    // 5. attention with folded mean
    attn_kernel<<<PP, 256>>>();

    // 6. final projections
    gemm_kernel<true, true><<<dim3(HH / BN, PP / BM), TPB>>>(
        pCtx, attn_out_w, attn_out_b, pTmp, PP, HH, HH, HH, HH, HH);
    gemm_kernel<true, true><<<dim3(HH / BN, PP / BM), TPB>>>(
        pTmp, path_proj_w, path_proj_b, out, PP, HH, HH, HH, HH, HH);
}

// round 5
// speedup vs baseline: 1.8293x; 1.0879x over previous
#include <cuda_runtime.h>
#include <cuda_bf16.h>
#include <math.h>

// Problem constants
#define PP    2048
#define KK    10
#define LL    3
#define EE    256
#define HH    512
#define G4    2048      // 4*H
#define NPK   20480     // P*K
#define NENT  10000
#define NREL  200

// ---------------- scratch (static device globals; no allocs) ----------------
__device__ float g_W1[G4 * EE];
__device__ float g_W2[G4 * EE];
__device__ float g_biasc[G4];
__device__ float g_Wc[HH * HH];          // path_proj_w @ attn_out_w
__device__ float g_bc2[HH];              // path_proj_w @ attn_out_b + path_proj_b
__device__ float g_rel_gate[NREL * G4];
__device__ float g_ent_gate[NENT * G4];
__device__ float g_h0[NPK * HH];         // permuted layout
__device__ float g_h1[NPK * HH];         // permuted layout
__device__ float g_c[NPK * HH];          // permuted layout
__device__ float g_pemb[NPK * HH];       // ORIGINAL layout
__device__ float g_qkv[NPK * 3 * HH];    // ORIGINAL layout
__device__ float g_ctxmean[PP * HH];

// length-sort state
__device__ int g_bins[4];
__device__ int g_off[4];
__device__ int g_cnt[3];                 // [0]=#len3, [1]=#len>=2, [2]=#len>=1
__device__ int g_perm[NPK];

__device__ __forceinline__ float sigf(float x) { return 1.0f / (1.0f + expf(-x)); }
__device__ __forceinline__ float4 ld4(const float* p) { return *reinterpret_cast<const float4*>(p); }

// ================= small legacy GEMM (precompute-sized problems) ============
#define BM 128
#define BN 64
#define BK 16
#define TPB 256

template <bool B_TRANS, bool BIAS>
__global__ void gemm_kernel(const float* __restrict__ A, const float* __restrict__ B,
                            const float* __restrict__ bias, float* __restrict__ C,
                            int M, int N, int Kd, int lda, int ldb, int ldc) {
    __shared__ float shA[BK][BM + 4];
    __shared__ float shB[BK][BN + 2];
    const int m0 = blockIdx.y * BM;
    const int n0 = blockIdx.x * BN;
    const int tid = threadIdx.x;
    const int jj = tid & 15;
    const int rg = tid >> 4;
    const int r0 = rg * 8;

    float acc[8][4];
#pragma unroll
    for (int i = 0; i < 8; i++)
#pragma unroll
        for (int q = 0; q < 4; q++) acc[i][q] = 0.0f;

    const int a_row = tid >> 2;
    const int a_k4  = (tid & 3) * 4;

    for (int k0 = 0; k0 < Kd; k0 += BK) {
#pragma unroll
        for (int hhalf = 0; hhalf < 2; hhalf++) {
            int r = a_row + hhalf * 64;
            int m = m0 + r;
            float4 v = make_float4(0.f, 0.f, 0.f, 0.f);
            if (m < M) v = ld4(&A[(size_t)m * lda + k0 + a_k4]);
            shA[a_k4 + 0][r] = v.x;
            shA[a_k4 + 1][r] = v.y;
            shA[a_k4 + 2][r] = v.z;
            shA[a_k4 + 3][r] = v.w;
        }
        if (B_TRANS) {
            int c  = tid >> 2;
            int k4 = (tid & 3) * 4;
            float4 v = ld4(&B[(size_t)(n0 + c) * ldb + k0 + k4]);
            shB[k4 + 0][c] = v.x;
            shB[k4 + 1][c] = v.y;
            shB[k4 + 2][c] = v.z;
            shB[k4 + 3][c] = v.w;
        } else {
            int kk2 = tid >> 4;
            int cc  = (tid & 15) * 4;
            float4 v = ld4(&B[(size_t)(k0 + kk2) * ldb + n0 + cc]);
            shB[kk2][cc + 0] = v.x;
            shB[kk2][cc + 1] = v.y;
            shB[kk2][cc + 2] = v.z;
            shB[kk2][cc + 3] = v.w;
        }
        __syncthreads();
#pragma unroll
        for (int k = 0; k < BK; k++) {
            float4 a01 = ld4(&shA[k][r0]);
            float4 a23 = ld4(&shA[k][r0 + 4]);
            float b0 = shB[k][jj], b1 = shB[k][jj + 16], b2 = shB[k][jj + 32], b3 = shB[k][jj + 48];
            float a[8] = {a01.x, a01.y, a01.z, a01.w, a23.x, a23.y, a23.z, a23.w};
#pragma unroll
            for (int i = 0; i < 8; i++) {
                acc[i][0] += a[i] * b0;
                acc[i][1] += a[i] * b1;
                acc[i][2] += a[i] * b2;
                acc[i][3] += a[i] * b3;
            }
        }
        __syncthreads();
    }

    float bv0 = 0.f, bv1 = 0.f, bv2 = 0.f, bv3 = 0.f;
    if (BIAS) {
        bv0 = bias[n0 + jj];
        bv1 = bias[n0 + jj + 16];
        bv2 = bias[n0 + jj + 32];
        bv3 = bias[n0 + jj + 48];
    }
#pragma unroll
    for (int i = 0; i < 8; i++) {
        int m = m0 + r0 + i;
        if (m < M) {
            float* crow = &C[(size_t)m * ldc + n0];
            crow[jj]      = acc[i][0] + bv0;
            crow[jj + 16] = acc[i][1] + bv1;
            crow[jj + 32] = acc[i][2] + bv2;
            crow[jj + 48] = acc[i][3] + bv3;
        }
    }
}

// ================= big double-buffered 128x128 GEMM machine =================
#define BM2 128
#define BN2 128
#define BK2 16

// ---- plain NT GEMM: C[M,N] = A[M,K] @ B[N,K]^T (+bias). N,K mult of 128/16.
template <bool BIAS>
__global__ __launch_bounds__(256, 2) void gemm_nt_big(
    const float* __restrict__ A, const float* __restrict__ B,
    const float* __restrict__ bias, float* __restrict__ C,
    int M, int Kd, int lda, int ldb, int ldc) {
    __shared__ float shA[2][BK2][BM2 + 4];
    __shared__ float shB[2][BK2][BN2 + 4];
    const int tid = threadIdx.x;
    const int m0 = blockIdx.y * BM2;
    const int n0 = blockIdx.x * BN2;
    const int jj = tid & 15, rg = tid >> 4;
    const int r0 = rg * 8, cb = jj * 4;
    const int lr = tid >> 2;
    const int k4 = (tid & 3) * 4;

    float acc[8][8];
#pragma unroll
    for (int i = 0; i < 8; i++)
#pragma unroll
        for (int q = 0; q < 8; q++) acc[i][q] = 0.f;

    float4 pA0, pA1, pB0, pB1;
    const float4 z4 = make_float4(0.f, 0.f, 0.f, 0.f);

    const int nt = Kd / BK2;
    // prologue
    {
        int k0 = 0;
        int m = m0 + lr;
        pA0 = (m < M) ? ld4(&A[(size_t)m * lda + k0 + k4]) : z4;
        m = m0 + lr + 64;
        pA1 = (m < M) ? ld4(&A[(size_t)m * lda + k0 + k4]) : z4;
        pB0 = ld4(&B[(size_t)(n0 + lr) * ldb + k0 + k4]);
        pB1 = ld4(&B[(size_t)(n0 + lr + 64) * ldb + k0 + k4]);
        shA[0][k4 + 0][lr] = pA0.x; shA[0][k4 + 1][lr] = pA0.y;
        shA[0][k4 + 2][lr] = pA0.z; shA[0][k4 + 3][lr] = pA0.w;
        shA[0][k4 + 0][lr + 64] = pA1.x; shA[0][k4 + 1][lr + 64] = pA1.y;
        shA[0][k4 + 2][lr + 64] = pA1.z; shA[0][k4 + 3][lr + 64] = pA1.w;
        shB[0][k4 + 0][lr] = pB0.x; shB[0][k4 + 1][lr] = pB0.y;
        shB[0][k4 + 2][lr] = pB0.z; shB[0][k4 + 3][lr] = pB0.w;
        shB[0][k4 + 0][lr + 64] = pB1.x; shB[0][k4 + 1][lr + 64] = pB1.y;
        shB[0][k4 + 2][lr + 64] = pB1.z; shB[0][k4 + 3][lr + 64] = pB1.w;
    }
    __syncthreads();
    int buf = 0;
    for (int t = 0; t < nt; t++) {
        if (t + 1 < nt) {
            int k0 = (t + 1) * BK2;
            int m = m0 + lr;
            pA0 = (m < M) ? ld4(&A[(size_t)m * lda + k0 + k4]) : z4;
            m = m0 + lr + 64;
            pA1 = (m < M) ? ld4(&A[(size_t)m * lda + k0 + k4]) : z4;
            pB0 = ld4(&B[(size_t)(n0 + lr) * ldb + k0 + k4]);
            pB1 = ld4(&B[(size_t)(n0 + lr + 64) * ldb + k0 + k4]);
        }
#pragma unroll
        for (int k = 0; k < BK2; k++) {
            float4 a0 = ld4(&shA[buf][k][r0]);
            float4 a1 = ld4(&shA[buf][k][r0 + 4]);
            float4 b0 = ld4(&shB[buf][k][cb]);
            float4 b1 = ld4(&shB[buf][k][cb + 64]);
            float av[8] = {a0.x, a0.y, a0.z, a0.w, a1.x, a1.y, a1.z, a1.w};
            float bv[8] = {b0.x, b0.y, b0.z, b0.w, b1.x, b1.y, b1.z, b1.w};
#pragma unroll
            for (int i = 0; i < 8; i++)
#pragma unroll
                for (int q = 0; q < 8; q++) acc[i][q] += av[i] * bv[q];
        }
        if (t + 1 < nt) {
            int nb = buf ^ 1;
            shA[nb][k4 + 0][lr] = pA0.x; shA[nb][k4 + 1][lr] = pA0.y;
            shA[nb][k4 + 2][lr] = pA0.z; shA[nb][k4 + 3][lr] = pA0.w;
            shA[nb][k4 + 0][lr + 64] = pA1.x; shA[nb][k4 + 1][lr + 64] = pA1.y;
            shA[nb][k4 + 2][lr + 64] = pA1.z; shA[nb][k4 + 3][lr + 64] = pA1.w;
            shB[nb][k4 + 0][lr] = pB0.x; shB[nb][k4 + 1][lr] = pB0.y;
            shB[nb][k4 + 2][lr] = pB0.z; shB[nb][k4 + 3][lr] = pB0.w;
            shB[nb][k4 + 0][lr + 64] = pB1.x; shB[nb][k4 + 1][lr + 64] = pB1.y;
            shB[nb][k4 + 2][lr + 64] = pB1.z; shB[nb][k4 + 3][lr + 64] = pB1.w;
        }
        __syncthreads();
        buf ^= 1;
    }

    float bvl[8];
#pragma unroll
    for (int q = 0; q < 8; q++) bvl[q] = 0.f;
    if (BIAS) {
#pragma unroll
        for (int q = 0; q < 4; q++) { bvl[q] = bias[n0 + cb + q]; bvl[4 + q] = bias[n0 + cb + 64 + q]; }
    }
#pragma unroll
    for (int i = 0; i < 8; i++) {
        int m = m0 + r0 + i;
        if (m < M) {
            float* crow = &C[(size_t)m * ldc + n0];
            *reinterpret_cast<float4*>(&crow[cb]) =
                make_float4(acc[i][0] + bvl[0], acc[i][1] + bvl[1], acc[i][2] + bvl[2], acc[i][3] + bvl[3]);
            *reinterpret_cast<float4*>(&crow[cb + 64]) =
                make_float4(acc[i][4] + bvl[4], acc[i][5] + bvl[5], acc[i][6] + bvl[6], acc[i][7] + bvl[7]);
        }
    }
}

// ---- QKV GEMM: rows gathered via perm, outputs scattered to original layout.
__global__ __launch_bounds__(256, 2) void qkv_gemm_big(
    const float* __restrict__ A /*pemb orig*/, const float* __restrict__ B /*[3H,H]*/,
    const float* __restrict__ bias, float* __restrict__ C /*qkv orig*/,
    const int* __restrict__ perm, const int* __restrict__ cntp) {
    const int m0 = blockIdx.y * BM2;
    if (m0 >= __ldg(cntp)) return;

    __shared__ float shA[2][BK2][BM2 + 4];
    __shared__ float shB[2][BK2][BN2 + 4];
    __shared__ int sPerm[BM2];
    const int tid = threadIdx.x;
    const int n0 = blockIdx.x * BN2;
    const int jj = tid & 15, rg = tid >> 4;
    const int r0 = rg * 8, cb = jj * 4;
    const int lr = tid >> 2;
    const int k4 = (tid & 3) * 4;

    if (tid < BM2) sPerm[tid] = perm[m0 + tid];
    __syncthreads();

    float acc[8][8];
#pragma unroll
    for (int i = 0; i < 8; i++)
#pragma unroll
        for (int q = 0; q < 8; q++) acc[i][q] = 0.f;

    float4 pA0, pA1, pB0, pB1;
    const int rowA0 = sPerm[lr];
    const int rowA1 = sPerm[lr + 64];
    const int nt = HH / BK2;
    {
        pA0 = ld4(&A[(size_t)rowA0 * HH + k4]);
        pA1 = ld4(&A[(size_t)rowA1 * HH + k4]);
        pB0 = ld4(&B[(size_t)(n0 + lr) * HH + k4]);
        pB1 = ld4(&B[(size_t)(n0 + lr + 64) * HH + k4]);
        shA[0][k4 + 0][lr] = pA0.x; shA[0][k4 + 1][lr] = pA0.y;
        shA[0][k4 + 2][lr] = pA0.z; shA[0][k4 + 3][lr] = pA0.w;
        shA[0][k4 + 0][lr + 64] = pA1.x; shA[0][k4 + 1][lr + 64] = pA1.y;
        shA[0][k4 + 2][lr + 64] = pA1.z; shA[0][k4 + 3][lr + 64] = pA1.w;
        shB[0][k4 + 0][lr] = pB0.x; shB[0][k4 + 1][lr] = pB0.y;
        shB[0][k4 + 2][lr] = pB0.z; shB[0][k4 + 3][lr] = pB0.w;
        shB[0][k4 + 0][lr + 64] = pB1.x; shB[0][k4 + 1][lr + 64] = pB1.y;
        shB[0][k4 + 2][lr + 64] = pB1.z; shB[0][k4 + 3][lr + 64] = pB1.w;
    }
    __syncthreads();
    int buf = 0;
    for (int t = 0; t < nt; t++) {
        if (t + 1 < nt) {
            int k0 = (t + 1) * BK2;
            pA0 = ld4(&A[(size_t)rowA0 * HH + k0 + k4]);
            pA1 = ld4(&A[(size_t)rowA1 * HH + k0 + k4]);
            pB0 = ld4(&B[(size_t)(n0 + lr) * HH + k0 + k4]);
            pB1 = ld4(&B[(size_t)(n0 + lr + 64) * HH + k0 + k4]);
        }
#pragma unroll
        for (int k = 0; k < BK2; k++) {
            float4 a0 = ld4(&shA[buf][k][r0]);
            float4 a1 = ld4(&shA[buf][k][r0 + 4]);
            float4 b0 = ld4(&shB[buf][k][cb]);
            float4 b1 = ld4(&shB[buf][k][cb + 64]);
            float av[8] = {a0.x, a0.y, a0.z, a0.w, a1.x, a1.y, a1.z, a1.w};
            float bv[8] = {b0.x, b0.y, b0.z, b0.w, b1.x, b1.y, b1.z, b1.w};
#pragma unroll
            for (int i = 0; i < 8; i++)
#pragma unroll
                for (int q = 0; q < 8; q++) acc[i][q] += av[i] * bv[q];
        }
        if (t + 1 < nt) {
            int nb = buf ^ 1;
            shA[nb][k4 + 0][lr] = pA0.x; shA[nb][k4 + 1][lr] = pA0.y;
            shA[nb][k4 + 2][lr] = pA0.z; shA[nb][k4 + 3][lr] = pA0.w;
            shA[nb][k4 + 0][lr + 64] = pA1.x; shA[nb][k4 + 1][lr + 64] = pA1.y;
            shA[nb][k4 + 2][lr + 64] = pA1.z; shA[nb][k4 + 3][lr + 64] = pA1.w;
            shB[nb][k4 + 0][lr] = pB0.x; shB[nb][k4 + 1][lr] = pB0.y;
            shB[nb][k4 + 2][lr] = pB0.z; shB[nb][k4 + 3][lr] = pB0.w;
            shB[nb][k4 + 0][lr + 64] = pB1.x; shB[nb][k4 + 1][lr + 64] = pB1.y;
            shB[nb][k4 + 2][lr + 64] = pB1.z; shB[nb][k4 + 3][lr + 64] = pB1.w;
        }
        __syncthreads();
        buf ^= 1;
    }

    float bvl[8];
#pragma unroll
    for (int q = 0; q < 4; q++) { bvl[q] = bias[n0 + cb + q]; bvl[4 + q] = bias[n0 + cb + 64 + q]; }
#pragma unroll
    for (int i = 0; i < 8; i++) {
        int orig = sPerm[r0 + i];
        float* crow = &C[(size_t)orig * (3 * HH) + n0];
        *reinterpret_cast<float4*>(&crow[cb]) =
            make_float4(acc[i][0] + bvl[0], acc[i][1] + bvl[1], acc[i][2] + bvl[2], acc[i][3] + bvl[3]);
        *reinterpret_cast<float4*>(&crow[cb + 64]) =
            make_float4(acc[i][4] + bvl[4], acc[i][5] + bvl[5], acc[i][6] + bvl[6], acc[i][7] + bvl[7]);
    }
}

// ---- fused LSTM step: gates = h_prev @ w_hh^T (+gathered inputs) -> cell ---
// smem col c (0..127) <-> w_hh row (c&3)*HH + j0 + (c>>2); thread cols are
// {4*jj+q} (j=j0+jj) and {64+4*jj+q} (j=j0+16+jj), q = gate i,f,g,o.
__global__ __launch_bounds__(256, 2) void lstm_step_big(
    const float* __restrict__ h_prev, float* __restrict__ h_next,
    const float* __restrict__ w_hh,
    const int* __restrict__ rel_idx, const int* __restrict__ ent_idx,
    const int* __restrict__ path_lens, int t,
    const int* __restrict__ perm, const int* __restrict__ cntp) {
    const int m0 = blockIdx.y * BM2;
    if (m0 >= __ldg(cntp)) return;

    __shared__ float shA[2][BK2][BM2 + 4];
    __shared__ float shB[2][BK2][BN2 + 4];
    const int tid = threadIdx.x;
    const int j0 = blockIdx.x * 32;
    const int jj = tid & 15, rg = tid >> 4;
    const int r0 = rg * 8, cb = jj * 4;
    const int lr = tid >> 2;
    const int k4 = (tid & 3) * 4;

    float acc[8][8];
#pragma unroll
    for (int i = 0; i < 8; i++)
#pragma unroll
        for (int q = 0; q < 8; q++) acc[i][q] = 0.f;

    // w_hh source rows for this thread's two B columns
    const int c0 = lr, c1 = lr + 64;
    const size_t wr0 = (size_t)((c0 & 3) * HH + j0 + (c0 >> 2)) * HH;
    const size_t wr1 = (size_t)((c1 & 3) * HH + j0 + (c1 >> 2)) * HH;

    float4 pA0, pA1, pB0, pB1;
    const int nt = HH / BK2;
    {
        pA0 = ld4(&h_prev[(size_t)(m0 + lr) * HH + k4]);
        pA1 = ld4(&h_prev[(size_t)(m0 + lr + 64) * HH + k4]);
        pB0 = ld4(&w_hh[wr0 + k4]);
        pB1 = ld4(&w_hh[wr1 + k4]);
        shA[0][k4 + 0][lr] = pA0.x; shA[0][k4 + 1][lr] = pA0.y;
        shA[0][k4 + 2][lr] = pA0.z; shA[0][k4 + 3][lr] = pA0.w;
        shA[0][k4 + 0][lr + 64] = pA1.x; shA[0][k4 + 1][lr + 64] = pA1.y;
        shA[0][k4 + 2][lr + 64] = pA1.z; shA[0][k4 + 3][lr + 64] = pA1.w;
        shB[0][k4 + 0][c0] = pB0.x; shB[0][k4 + 1][c0] = pB0.y;
        shB[0][k4 + 2][c0] = pB0.z; shB[0][k4 + 3][c0] = pB0.w;
        shB[0][k4 + 0][c1] = pB1.x; shB[0][k4 + 1][c1] = pB1.y;
        shB[0][k4 + 2][c1] = pB1.z; shB[0][k4 + 3][c1] = pB1.w;
    }
    __syncthreads();
    int buf = 0;
    for (int tt = 0; tt < nt; tt++) {
        if (tt + 1 < nt) {
            int k0 = (tt + 1) * BK2;
            pA0 = ld4(&h_prev[(size_t)(m0 + lr) * HH + k0 + k4]);
            pA1 = ld4(&h_prev[(size_t)(m0 + lr + 64) * HH + k0 + k4]);
            pB0 = ld4(&w_hh[wr0 + k0 + k4]);
            pB1 = ld4(&w_hh[wr1 + k0 + k4]);
        }
#pragma unroll
        for (int k = 0; k < BK2; k++) {
            float4 a0 = ld4(&shA[buf][k][r0]);
            float4 a1 = ld4(&shA[buf][k][r0 + 4]);
            float4 b0 = ld4(&shB[buf][k][cb]);
            float4 b1 = ld4(&shB[buf][k][cb + 64]);
            float av[8] = {a0.x, a0.y, a0.z, a0.w, a1.x, a1.y, a1.z, a1.w};
            float bv[8] = {b0.x, b0.y, b0.z, b0.w, b1.x, b1.y, b1.z, b1.w};
#pragma unroll
            for (int i = 0; i < 8; i++)
#pragma unroll
                for (int q = 0; q < 8; q++) acc[i][q] += av[i] * bv[q];
        }
        if (tt + 1 < nt) {
            int nb = buf ^ 1;
            shA[nb][k4 + 0][lr] = pA0.x; shA[nb][k4 + 1][lr] = pA0.y;
            shA[nb][k4 + 2][lr] = pA0.z; shA[nb][k4 + 3][lr] = pA0.w;
            shA[nb][k4 + 0][lr + 64] = pA1.x; shA[nb][k4 + 1][lr + 64] = pA1.y;
            shA[nb][k4 + 2][lr + 64] = pA1.z; shA[nb][k4 + 3][lr + 64] = pA1.w;
            shB[nb][k4 + 0][c0] = pB0.x; shB[nb][k4 + 1][c0] = pB0.y;
            shB[nb][k4 + 2][c0] = pB0.z; shB[nb][k4 + 3][c0] = pB0.w;
            shB[nb][k4 + 0][c1] = pB1.x; shB[nb][k4 + 1][c1] = pB1.y;
            shB[nb][k4 + 2][c1] = pB1.z; shB[nb][k4 + 3][c1] = pB1.w;
        }
        __syncthreads();
        buf ^= 1;
    }

    const int j1 = j0 + jj;        // acc[i][0..3]
    const int j2 = j0 + 16 + jj;   // acc[i][4..7]
    float bc[8];
#pragma unroll
    for (int q = 0; q < 4; q++) { bc[q] = g_biasc[q * HH + j1]; bc[4 + q] = g_biasc[q * HH + j2]; }

#pragma unroll
    for (int i = 0; i < 8; i++) {
        const int n = m0 + r0 + i;              // permuted row
        const int orig = perm[n];
        const int ridx = rel_idx[orig * LL + t];
        const int eidx = ent_idx[orig * LL + t];
        const float* rgp = &g_rel_gate[(size_t)ridx * G4];
        const float* egp = &g_ent_gate[(size_t)eidx * G4];
        const bool emit = (path_lens[orig] == t + 1);
#pragma unroll
        for (int h = 0; h < 2; h++) {
            const int j = h ? j2 : j1;
            float gi = acc[i][4 * h + 0] + rgp[j]          + egp[j]          + bc[4 * h + 0];
            float gf = acc[i][4 * h + 1] + rgp[HH + j]     + egp[HH + j]     + bc[4 * h + 1];
            float gg = acc[i][4 * h + 2] + rgp[2 * HH + j] + egp[2 * HH + j] + bc[4 * h + 2];
            float go = acc[i][4 * h + 3] + rgp[3 * HH + j] + egp[3 * HH + j] + bc[4 * h + 3];
            size_t off = (size_t)n * HH + j;
            float cn = sigf(gf) * g_c[off] + sigf(gi) * tanhf(gg);
            float hn = sigf(go) * tanhf(cn);
            g_c[off] = cn;
            h_next[off] = hn;
            if (emit) g_pemb[(size_t)orig * HH + j] = hn;
        }
    }
}

// ---------------- combined gate bias --------------------------------------
__global__ void biasc_kernel(const float* __restrict__ kg_proj_b, const float* __restrict__ w_ih,
                             const float* __restrict__ b_ih, const float* __restrict__ b_hh) {
    int g = blockIdx.x;
    float s = 0.f;
    const float* row = &w_ih[(size_t)g * (2 * HH)];
    for (int h = threadIdx.x; h < HH; h += 128) s += kg_proj_b[h] * (row[h] + row[HH + h]);
    __shared__ float red[128];
    red[threadIdx.x] = s;
    __syncthreads();
    for (int off = 64; off > 0; off >>= 1) {
        if (threadIdx.x < off) red[threadIdx.x] += red[threadIdx.x + off];
        __syncthreads();
    }
    if (threadIdx.x == 0) g_biasc[g] = red[0] + b_ih[g] + b_hh[g];
}

// ---------------- folded output bias: bc2 = path_proj_w @ attn_out_b + path_proj_b
__global__ void biasfold_kernel(const float* __restrict__ ppw, const float* __restrict__ aob,
                                const float* __restrict__ ppb) {
    int i = blockIdx.x;
    float s = 0.f;
    const float* row = &ppw[(size_t)i * HH];
    for (int jx = threadIdx.x; jx < HH; jx += 128) s += row[jx] * aob[jx];
    __shared__ float red[128];
    red[threadIdx.x] = s;
    __syncthreads();
    for (int off = 64; off > 0; off >>= 1) {
        if (threadIdx.x < off) red[threadIdx.x] += red[threadIdx.x + off];
        __syncthreads();
    }
    if (threadIdx.x == 0) g_bc2[i] = red[0] + ppb[i];
}

// ---------------- counting sort by path length (descending) ----------------
__global__ void sort_init() {
    if (threadIdx.x < 4) g_bins[threadIdx.x] = 0;
}
__global__ void sort_count(const int* __restrict__ lens) {
    int n = blockIdx.x * blockDim.x + threadIdx.x;
    if (n < NPK) {
        int l = lens[n]; l = max(0, min(3, l));
        atomicAdd(&g_bins[3 - l], 1);
    }
}
__global__ void sort_prefix() {
    int c0 = g_bins[0], c1 = g_bins[1], c2 = g_bins[2];
    g_off[0] = 0; g_off[1] = c0; g_off[2] = c0 + c1; g_off[3] = c0 + c1 + c2;
    g_cnt[0] = c0; g_cnt[1] = c0 + c1; g_cnt[2] = c0 + c1 + c2;
}
__global__ void sort_scatter(const int* __restrict__ lens) {
    int n = blockIdx.x * blockDim.x + threadIdx.x;
    if (n < NPK) {
        int l = lens[n]; l = max(0, min(3, l));
        int pos = atomicAdd(&g_off[3 - l], 1);
        g_perm[pos] = n;
    }
}

// ---------------- LSTM step 0 (h=c=0), permuted layout ---------------------
__global__ void step0_kernel(const int* __restrict__ rel_idx, const int* __restrict__ ent_idx,
                             const int* __restrict__ path_lens, const int* __restrict__ perm) {
    int n = blockIdx.x;
    int orig = perm[n];
    int j = threadIdx.x * 4;
    int ridx = rel_idx[orig * LL + 0];
    int eidx = ent_idx[orig * LL + 0];
    int len  = path_lens[orig];
    const float* rgp = &g_rel_gate[(size_t)ridx * G4];
    const float* egp = &g_ent_gate[(size_t)eidx * G4];

    float4 h4, c4;
    float* hv = &h4.x;
    float* cv = &c4.x;
#pragma unroll
    for (int u = 0; u < 4; u++) {
        int jc = j + u;
        float gi = rgp[jc]          + egp[jc]          + g_biasc[jc];
        float gg = rgp[2 * HH + jc] + egp[2 * HH + jc] + g_biasc[2 * HH + jc];
        float go = rgp[3 * HH + jc] + egp[3 * HH + jc] + g_biasc[3 * HH + jc];
        float cn = sigf(gi) * tanhf(gg);
        hv[u] = sigf(go) * tanhf(cn);
        cv[u] = cn;
    }
    size_t offp = (size_t)n * HH + j;
    *reinterpret_cast<float4*>(&g_h0[offp]) = h4;
    *reinterpret_cast<float4*>(&g_c[offp])  = c4;
    size_t offo = (size_t)orig * HH + j;
    if (len == 1) {
        *reinterpret_cast<float4*>(&g_pemb[offo]) = h4;
    } else if (len == 0) {
        *reinterpret_cast<float4*>(&g_pemb[offo]) = make_float4(0.f, 0.f, 0.f, 0.f);
    }
}

// qkv rows for len==0 paths: pemb row is zero -> qkv row = bias
__global__ void qkv_fill_kernel(const float* __restrict__ bias,
                                const int* __restrict__ perm, const int* __restrict__ cntp) {
    int m = blockIdx.x;
    if (m < __ldg(cntp)) return;
    int orig = perm[m];
    float4* row = reinterpret_cast<float4*>(&g_qkv[(size_t)orig * (3 * HH)]);
    const float4* b4 = reinterpret_cast<const float4*>(bias);
    for (int i = threadIdx.x; i < (3 * HH) / 4; i += blockDim.x) row[i] = b4[i];
}

// ---------------- per-pair attention; mean over K folded into column-sum ----
__global__ void attn_kernel() {
    int p = blockIdx.x;
    int tid = threadIdx.x;
    __shared__ float sq[KK][128], sk[KK][128], sv[KK][128];
    __shared__ float sc[KK][KK + 2];
    __shared__ float wcol[KK];

    for (int hd = 0; hd < 4; hd++) {
        for (int i = tid; i < KK * 128; i += 256) {
            int a = i >> 7, d = i & 127;
            size_t base = (size_t)(p * KK + a) * (3 * HH) + hd * 128 + d;
            sq[a][d] = g_qkv[base];
            sk[a][d] = g_qkv[base + HH];
            sv[a][d] = g_qkv[base + 2 * HH];
        }
        __syncthreads();
        if (tid < KK * KK) {
            int a = tid / KK, b = tid % KK;
            float s = 0.f;
#pragma unroll 8
            for (int d = 0; d < 128; d++) s += sq[a][d] * sk[b][d];
            sc[a][b] = s * 0.08838834764831845f;
        }
        __syncthreads();
        if (tid < KK) {
            int a = tid;
            float mx = -1e30f;
            for (int b = 0; b < KK; b++) mx = fmaxf(mx, sc[a][b]);
            float e[KK], sum = 0.f;
            for (int b = 0; b < KK; b++) { e[b] = expf(sc[a][b] - mx); sum += e[b]; }
            float inv = 1.f / sum;
            for (int b = 0; b < KK; b++) sc[a][b] = e[b] * inv;
        }
        __syncthreads();
        if (tid < KK) {
            int b = tid;
            float s = 0.f;
            for (int a = 0; a < KK; a++) s += sc[a][b];
            wcol[b] = s * 0.1f;
        }
        __syncthreads();
        if (tid < 128) {
            int d = tid;
            float s = 0.f;
#pragma unroll
            for (int b = 0; b < KK; b++) s += wcol[b] * sv[b][d];
            g_ctxmean[(size_t)p * HH + hd * 128 + d] = s;
        }
        __syncthreads();
    }
}

// ---------------- launch --------------------------------------------------
extern "C" void kernel_launch(void* const* d_in, const int* in_sizes, int n_in,
                              void* d_out, int out_size) {
    const int*   rel_idx     = (const int*)d_in[0];
    const int*   ent_idx     = (const int*)d_in[1];
    const int*   path_lens   = (const int*)d_in[2];
    const float* rel_table   = (const float*)d_in[3];
    const float* ent_table   = (const float*)d_in[4];
    const float* kg_proj_w   = (const float*)d_in[5];
    const float* kg_proj_b   = (const float*)d_in[6];
    const float* w_ih        = (const float*)d_in[7];
    const float* w_hh        = (const float*)d_in[8];
    const float* b_ih        = (const float*)d_in[9];
    const float* b_hh        = (const float*)d_in[10];
    const float* attn_in_w   = (const float*)d_in[11];
    const float* attn_in_b   = (const float*)d_in[12];
    const float* attn_out_w  = (const float*)d_in[13];
    const float* attn_out_b  = (const float*)d_in[14];
    const float* path_proj_w = (const float*)d_in[15];
    const float* path_proj_b = (const float*)d_in[16];
    float* out = (float*)d_out;

    float *pW1, *pW2, *pRel, *pEnt, *pH0, *pH1, *pPemb, *pQkv, *pCtx, *pWc, *pBc2;
    int *pPerm, *pCnt;
    cudaGetSymbolAddress((void**)&pW1, g_W1);
    cudaGetSymbolAddress((void**)&pW2, g_W2);
    cudaGetSymbolAddress((void**)&pRel, g_rel_gate);
    cudaGetSymbolAddress((void**)&pEnt, g_ent_gate);
    cudaGetSymbolAddress((void**)&pH0, g_h0);
    cudaGetSymbolAddress((void**)&pH1, g_h1);
    cudaGetSymbolAddress((void**)&pPemb, g_pemb);
    cudaGetSymbolAddress((void**)&pQkv, g_qkv);
    cudaGetSymbolAddress((void**)&pCtx, g_ctxmean);
    cudaGetSymbolAddress((void**)&pWc, g_Wc);
    cudaGetSymbolAddress((void**)&pBc2, g_bc2);
    cudaGetSymbolAddress((void**)&pPerm, g_perm);
    cudaGetSymbolAddress((void**)&pCnt, g_cnt);

    // 0. counting sort by path length (descending)
    sort_init<<<1, 32>>>();
    sort_count<<<(NPK + 255) / 256, 256>>>(path_lens);
    sort_prefix<<<1, 1>>>();
    sort_scatter<<<(NPK + 255) / 256, 256>>>(path_lens);

    // 1. folded weights + biases (small precompute, legacy kernel)
    {
        dim3 grid(EE / BN, G4 / BM);
        gemm_kernel<false, false><<<grid, TPB>>>(w_ih,      kg_proj_w, nullptr, pW1,
                                                 G4, EE, HH, 2 * HH, EE, EE);
        gemm_kernel<false, false><<<grid, TPB>>>(w_ih + HH, kg_proj_w, nullptr, pW2,
                                                 G4, EE, HH, 2 * HH, EE, EE);
    }
    biasc_kernel<<<G4, 128>>>(kg_proj_b, w_ih, b_ih, b_hh);
    // folded output projection: Wc = path_proj_w @ attn_out_w, bc2 = ppw@aob + ppb
    gemm_kernel<false, false><<<dim3(HH / BN, HH / BM), TPB>>>(
        path_proj_w, attn_out_w, nullptr, pWc, HH, HH, HH, HH, HH, HH);
    biasfold_kernel<<<HH, 128>>>(path_proj_w, attn_out_b, path_proj_b);

    // 2. per-entity gate tables (big machine)
    gemm_nt_big<false><<<dim3(G4 / BN2, (NENT + BM2 - 1) / BM2), 256>>>(
        ent_table, pW2, nullptr, pEnt, NENT, EE, EE, EE, G4);
    gemm_nt_big<false><<<dim3(G4 / BN2, (NREL + BM2 - 1) / BM2), 256>>>(
        rel_table, pW1, nullptr, pRel, NREL, EE, EE, EE, G4);

    // 3. LSTM: step 0 (gather) on all rows; steps 1,2 on compacted prefix
    step0_kernel<<<NPK, 128>>>(rel_idx, ent_idx, path_lens, pPerm);
    lstm_step_big<<<dim3(G4 / BN2, NPK / BM2), 256>>>(pH0, pH1, w_hh, rel_idx, ent_idx,
                                                      path_lens, 1, pPerm, pCnt + 1);
    lstm_step_big<<<dim3(G4 / BN2, NPK / BM2), 256>>>(pH1, pH0, w_hh, rel_idx, ent_idx,
                                                      path_lens, 2, pPerm, pCnt + 0);

    // 4. QKV: GEMM on len>0 rows (gathered), bias-fill for len==0 rows
    qkv_gemm_big<<<dim3(3 * HH / BN2, NPK / BM2), 256>>>(
        pPemb, attn_in_w, attn_in_b, pQkv, pPerm, pCnt + 2);
    qkv_fill_kernel<<<NPK, 128>>>(attn_in_b, pPerm, pCnt + 2);

    // 5. attention with folded mean
    attn_kernel<<<PP, 256>>>();

    // 6. single folded output projection: out = ctx_mean @ Wc^T + bc2
    gemm_nt_big<true><<<dim3(HH / BN2, PP / BM2), 256>>>(
        pCtx, pWc, pBc2, out, PP, HH, HH, HH, HH);
}

// round 10
// speedup vs baseline: 3.4546x; 1.8886x over previous
#include <cuda_runtime.h>
#include <cuda_bf16.h>
#include <math.h>
#include <stdint.h>

// Problem constants
#define PP    2048
#define KK    10
#define LL    3
#define EE    256
#define HH    512
#define G4    2048      // 4*H
#define NPK   20480     // P*K
#define NENT  10000
#define NREL  200

// ---------------- scratch (static device globals; no allocs) ----------------
__device__ float g_W1[G4 * EE];          // tf32-rounded
__device__ float g_W2[G4 * EE];          // tf32-rounded
__device__ float g_biasc[G4];
__device__ float g_Wc[HH * HH];          // tf32-rounded (path_proj_w @ attn_out_w)
__device__ float g_bc2[HH];
__device__ float g_rel_gate[NREL * G4];
__device__ float g_ent_gate[NENT * G4];
__device__ float g_h0[NPK * HH];         // permuted layout, tf32-rounded
__device__ float g_h1[NPK * HH];         // permuted layout, tf32-rounded
__device__ float g_c[NPK * HH];          // permuted layout, exact fp32
__device__ float g_pemb[NPK * HH];       // PERMUTED layout, tf32-rounded
__device__ float g_gates[NPK * G4];      // permuted layout gate pre-activations
__device__ float g_qkv[NPK * 3 * HH];    // ORIGINAL layout
__device__ float g_ctxmean[PP * HH];     // tf32-rounded
// tf32-rounded operand copies
__device__ float g_whr[G4 * HH];
__device__ float g_aiw[3 * HH * HH];
__device__ float g_entr[NENT * EE];
__device__ float g_relr[NREL * EE];

// length-sort state
__device__ int g_bins[4];
__device__ int g_off[4];
__device__ int g_cnt[3];                 // [0]=#len3, [1]=#len>=2, [2]=#len>=1
__device__ int g_perm[NPK];

__device__ __forceinline__ float sigf(float x) { return 1.0f / (1.0f + expf(-x)); }
__device__ __forceinline__ float4 ld4(const float* p) { return *reinterpret_cast<const float4*>(p); }
__device__ __forceinline__ float tf32r(float x) {
    uint32_t r;
    asm("cvt.rna.tf32.f32 %0, %1;" : "=r"(r) : "f"(x));
    return __uint_as_float(r);
}
__device__ __forceinline__ uint32_t smem_u32(const void* p) {
    uint32_t a;
    asm("{ .reg .u64 tmp; cvta.to.shared.u64 tmp, %1; cvt.u32.u64 %0, tmp; }" : "=r"(a) : "l"(p));
    return a;
}
__device__ __forceinline__ void cp16(uint32_t dst, const void* src) {
    asm volatile("cp.async.cg.shared.global [%0], [%1], 16;" :: "r"(dst), "l"(src) : "memory");
}
__device__ __forceinline__ void mma_tf32(float* c, const uint32_t* a, const uint32_t* b) {
    asm volatile(
        "mma.sync.aligned.m16n8k8.row.col.f32.tf32.tf32.f32 "
        "{%0,%1,%2,%3}, {%4,%5,%6,%7}, {%8,%9}, {%0,%1,%2,%3};"
        : "+f"(c[0]), "+f"(c[1]), "+f"(c[2]), "+f"(c[3])
        : "r"(a[0]), "r"(a[1]), "r"(a[2]), "r"(a[3]), "r"(b[0]), "r"(b[1]));
}

// ==================== mma.sync tf32 GEMM: C[M,N] = A[M,K] @ B[N,K]^T ========
// CTA tile 128x128, BK=32 double-buffered via cp.async. ldb == Kd.
// Inputs A,B must be pre-rounded to tf32 and ALREADY in GEMM row space.
// cntp: dynamic M cap. cmap: C-row scatter map (EPILOGUE ONLY — A is read
// directly at row r; do NOT gather A through cmap).
// smem: [0,512) perm, buffers at 1024: A0,B0,A1,B1 each 128*36*4 = 18432 B.
#define MG_STRIDE 36
#define MG_BUF    18432
#define MG_SMEM   (1024 + 4 * MG_BUF)
__global__ __launch_bounds__(256, 2) void mma_gemm(
    const float* __restrict__ A, int lda,
    const float* __restrict__ B,
    const float* __restrict__ bias,
    float* __restrict__ C, int ldc,
    int M, int Kd,
    const int* __restrict__ cntp,
    const int* __restrict__ cmap) {
    extern __shared__ char smem[];
    const int tid = threadIdx.x;
    const int wid = tid >> 5;
    const int lane = tid & 31;

    int Meff = M;
    if (cntp) { int cv = __ldg(cntp); Meff = (cv < M) ? cv : M; }
    const int m0 = blockIdx.y * 128;
    if (m0 >= Meff) return;
    const int n0 = blockIdx.x * 128;

    int* sPerm = reinterpret_cast<int*>(smem);
    float* bufA[2] = { reinterpret_cast<float*>(smem + 1024),
                       reinterpret_cast<float*>(smem + 1024 + 2 * MG_BUF) };
    float* bufB[2] = { reinterpret_cast<float*>(smem + 1024 + MG_BUF),
                       reinterpret_cast<float*>(smem + 1024 + 3 * MG_BUF) };
    uint32_t sbA[2] = { smem_u32(bufA[0]), smem_u32(bufA[1]) };
    uint32_t sbB[2] = { smem_u32(bufB[0]), smem_u32(bufB[1]) };

    if (cmap && tid < 128) sPerm[tid] = cmap[m0 + tid];
    __syncthreads();

    // staging source rows (fixed across chunks). A read DIRECTLY at row r.
    const int c4 = tid & 7;
    const float* srcA[4];
    const float* srcB[4];
    int dstOff[4];
#pragma unroll
    for (int i = 0; i < 4; i++) {
        int row = i * 32 + (tid >> 3);
        int r = m0 + row;
        if (r > Meff - 1) r = Meff - 1;
        srcA[i] = &A[(size_t)r * lda + c4 * 4];
        srcB[i] = &B[(size_t)(n0 + row) * Kd + c4 * 4];
        dstOff[i] = row * (MG_STRIDE * 4) + c4 * 16;
    }

    const int nch = Kd / 32;
    // stage chunk 0
    {
#pragma unroll
        for (int i = 0; i < 4; i++) {
            cp16(sbA[0] + dstOff[i], srcA[i]);
            cp16(sbB[0] + dstOff[i], srcB[i]);
        }
        asm volatile("cp.async.commit_group;" ::: "memory");
    }

    float acc[4][4][4];
#pragma unroll
    for (int mi = 0; mi < 4; mi++)
#pragma unroll
        for (int ni = 0; ni < 4; ni++)
#pragma unroll
            for (int q = 0; q < 4; q++) acc[mi][ni][q] = 0.f;

    const int g = lane >> 2, t = lane & 3;
    const int wm = wid >> 2, wn = wid & 3;

    for (int c = 0; c < nch; c++) {
        if (c + 1 < nch) {
            const int b = (c + 1) & 1;
            const int k0 = (c + 1) * 32;
#pragma unroll
            for (int i = 0; i < 4; i++) {
                cp16(sbA[b] + dstOff[i], srcA[i] + k0);
                cp16(sbB[b] + dstOff[i], srcB[i] + k0);
            }
            asm volatile("cp.async.commit_group;" ::: "memory");
            asm volatile("cp.async.wait_group 1;" ::: "memory");
        } else {
            asm volatile("cp.async.wait_group 0;" ::: "memory");
        }
        __syncthreads();

        const int b = c & 1;
        const uint32_t* As = reinterpret_cast<const uint32_t*>(bufA[b]);
        const uint32_t* Bs = reinterpret_cast<const uint32_t*>(bufB[b]);
#pragma unroll
        for (int k8 = 0; k8 < 4; k8++) {
            const int kc = k8 * 8 + t;
            uint32_t af[4][4];
#pragma unroll
            for (int mi = 0; mi < 4; mi++) {
                const uint32_t* ap = As + (wm * 64 + mi * 16 + g) * MG_STRIDE + kc;
                af[mi][0] = ap[0];
                af[mi][1] = ap[8 * MG_STRIDE];
                af[mi][2] = ap[4];
                af[mi][3] = ap[8 * MG_STRIDE + 4];
            }
            uint32_t bf[4][2];
#pragma unroll
            for (int ni = 0; ni < 4; ni++) {
                const uint32_t* bp = Bs + (wn * 32 + ni * 8 + g) * MG_STRIDE + kc;
                bf[ni][0] = bp[0];
                bf[ni][1] = bp[4];
            }
#pragma unroll
            for (int mi = 0; mi < 4; mi++)
#pragma unroll
                for (int ni = 0; ni < 4; ni++)
                    mma_tf32(acc[mi][ni], af[mi], bf[ni]);
        }
        __syncthreads();
    }

    // epilogue: c0=(g,2t) c1=(g,2t+1) c2=(g+8,2t) c3=(g+8,2t+1)
#pragma unroll
    for (int ni = 0; ni < 4; ni++) {
        const int col = n0 + wn * 32 + ni * 8 + 2 * t;
        float b0 = 0.f, b1 = 0.f;
        if (bias) { b0 = bias[col]; b1 = bias[col + 1]; }
#pragma unroll
        for (int mi = 0; mi < 4; mi++) {
            const int r0 = m0 + wm * 64 + mi * 16 + g;
            const int r1 = r0 + 8;
            if (r0 < Meff) {
                int ri = cmap ? sPerm[r0 - m0] : r0;
                float2 v = make_float2(acc[mi][ni][0] + b0, acc[mi][ni][1] + b1);
                *reinterpret_cast<float2*>(&C[(size_t)ri * ldc + col]) = v;
            }
            if (r1 < Meff) {
                int ri = cmap ? sPerm[r1 - m0] : r1;
                float2 v = make_float2(acc[mi][ni][2] + b0, acc[mi][ni][3] + b1);
                *reinterpret_cast<float2*>(&C[(size_t)ri * ldc + col]) = v;
            }
        }
    }
}

// ---------------- tf32 rounding copy ---------------------------------------
__global__ void round_tf32_kernel(const float* __restrict__ in, float* __restrict__ out, int n4) {
    int i = blockIdx.x * blockDim.x + threadIdx.x;
    if (i < n4) {
        float4 v = ld4(&in[i * 4]);
        v.x = tf32r(v.x); v.y = tf32r(v.y); v.z = tf32r(v.z); v.w = tf32r(v.w);
        *reinterpret_cast<float4*>(&out[i * 4]) = v;
    }
}

// ================= small fp32 GEMM (precompute, NN form), optional rounding =
#define BM 128
#define BN 64
#define BK 16
#define TPB 256

template <bool ROUND>
__global__ void gemm_nn_small(const float* __restrict__ A, const float* __restrict__ B,
                              float* __restrict__ C,
                              int M, int N, int Kd, int lda, int ldb, int ldc) {
    __shared__ float shA[BK][BM + 4];
    __shared__ float shB[BK][BN + 2];
    const int m0 = blockIdx.y * BM;
    const int n0 = blockIdx.x * BN;
    const int tid = threadIdx.x;
    const int jj = tid & 15;
    const int rg = tid >> 4;
    const int r0 = rg * 8;

    float acc[8][4];
#pragma unroll
    for (int i = 0; i < 8; i++)
#pragma unroll
        for (int q = 0; q < 4; q++) acc[i][q] = 0.0f;

    const int a_row = tid >> 2;
    const int a_k4  = (tid & 3) * 4;

    for (int k0 = 0; k0 < Kd; k0 += BK) {
#pragma unroll
        for (int hhalf = 0; hhalf < 2; hhalf++) {
            int r = a_row + hhalf * 64;
            int m = m0 + r;
            float4 v = make_float4(0.f, 0.f, 0.f, 0.f);
            if (m < M) v = ld4(&A[(size_t)m * lda + k0 + a_k4]);
            shA[a_k4 + 0][r] = v.x;
            shA[a_k4 + 1][r] = v.y;
            shA[a_k4 + 2][r] = v.z;
            shA[a_k4 + 3][r] = v.w;
        }
        {
            int kk2 = tid >> 4;
            int cc  = (tid & 15) * 4;
            float4 v = ld4(&B[(size_t)(k0 + kk2) * ldb + n0 + cc]);
            shB[kk2][cc + 0] = v.x;
            shB[kk2][cc + 1] = v.y;
            shB[kk2][cc + 2] = v.z;
            shB[kk2][cc + 3] = v.w;
        }
        __syncthreads();
#pragma unroll
        for (int k = 0; k < BK; k++) {
            float4 a01 = ld4(&shA[k][r0]);
            float4 a23 = ld4(&shA[k][r0 + 4]);
            float b0 = shB[k][jj], b1 = shB[k][jj + 16], b2 = shB[k][jj + 32], b3 = shB[k][jj + 48];
            float a[8] = {a01.x, a01.y, a01.z, a01.w, a23.x, a23.y, a23.z, a23.w};
#pragma unroll
            for (int i = 0; i < 8; i++) {
                acc[i][0] += a[i] * b0;
                acc[i][1] += a[i] * b1;
                acc[i][2] += a[i] * b2;
                acc[i][3] += a[i] * b3;
            }
        }
        __syncthreads();
    }
#pragma unroll
    for (int i = 0; i < 8; i++) {
        int m = m0 + r0 + i;
        if (m < M) {
            float* crow = &C[(size_t)m * ldc + n0];
            if (ROUND) {
                crow[jj]      = tf32r(acc[i][0]);
                crow[jj + 16] = tf32r(acc[i][1]);
                crow[jj + 32] = tf32r(acc[i][2]);
                crow[jj + 48] = tf32r(acc[i][3]);
            } else {
                crow[jj]      = acc[i][0];
                crow[jj + 16] = acc[i][1];
                crow[jj + 32] = acc[i][2];
                crow[jj + 48] = acc[i][3];
            }
        }
    }
}

// ---------------- combined gate bias --------------------------------------
__global__ void biasc_kernel(const float* __restrict__ kg_proj_b, const float* __restrict__ w_ih,
                             const float* __restrict__ b_ih, const float* __restrict__ b_hh) {
    int g = blockIdx.x;
    float s = 0.f;
    const float* row = &w_ih[(size_t)g * (2 * HH)];
    for (int h = threadIdx.x; h < HH; h += 128) s += kg_proj_b[h] * (row[h] + row[HH + h]);
    __shared__ float red[128];
    red[threadIdx.x] = s;
    __syncthreads();
    for (int off = 64; off > 0; off >>= 1) {
        if (threadIdx.x < off) red[threadIdx.x] += red[threadIdx.x + off];
        __syncthreads();
    }
    if (threadIdx.x == 0) g_biasc[g] = red[0] + b_ih[g] + b_hh[g];
}

// ---------------- folded output bias ---------------------------------------
__global__ void biasfold_kernel(const float* __restrict__ ppw, const float* __restrict__ aob,
                                const float* __restrict__ ppb) {
    int i = blockIdx.x;
    float s = 0.f;
    const float* row = &ppw[(size_t)i * HH];
    for (int jx = threadIdx.x; jx < HH; jx += 128) s += row[jx] * aob[jx];
    __shared__ float red[128];
    red[threadIdx.x] = s;
    __syncthreads();
    for (int off = 64; off > 0; off >>= 1) {
        if (threadIdx.x < off) red[threadIdx.x] += red[threadIdx.x + off];
        __syncthreads();
    }
    if (threadIdx.x == 0) g_bc2[i] = red[0] + ppb[i];
}

// ---------------- counting sort by path length (descending) ----------------
__global__ void sort_init() {
    if (threadIdx.x < 4) g_bins[threadIdx.x] = 0;
}
__global__ void sort_count(const int* __restrict__ lens) {
    int n = blockIdx.x * blockDim.x + threadIdx.x;
    if (n < NPK) {
        int l = lens[n]; l = max(0, min(3, l));
        atomicAdd(&g_bins[3 - l], 1);
    }
}
__global__ void sort_prefix() {
    int c0 = g_bins[0], c1 = g_bins[1], c2 = g_bins[2];
    g_off[0] = 0; g_off[1] = c0; g_off[2] = c0 + c1; g_off[3] = c0 + c1 + c2;
    g_cnt[0] = c0; g_cnt[1] = c0 + c1; g_cnt[2] = c0 + c1 + c2;
}
__global__ void sort_scatter(const int* __restrict__ lens) {
    int n = blockIdx.x * blockDim.x + threadIdx.x;
    if (n < NPK) {
        int l = lens[n]; l = max(0, min(3, l));
        int pos = atomicAdd(&g_off[3 - l], 1);
        g_perm[pos] = n;
    }
}

// ---------------- LSTM step 0 (h=c=0), permuted layout ---------------------
__global__ void step0_kernel(const int* __restrict__ rel_idx, const int* __restrict__ ent_idx,
                             const int* __restrict__ path_lens, const int* __restrict__ perm) {
    int n = blockIdx.x;
    int orig = perm[n];
    int j = threadIdx.x * 4;
    int ridx = rel_idx[orig * LL + 0];
    int eidx = ent_idx[orig * LL + 0];
    int len  = path_lens[orig];
    const float* rgp = &g_rel_gate[(size_t)ridx * G4];
    const float* egp = &g_ent_gate[(size_t)eidx * G4];

    float4 h4, c4;
    float* hv = &h4.x;
    float* cv = &c4.x;
#pragma unroll
    for (int u = 0; u < 4; u++) {
        int jc = j + u;
        float gi = rgp[jc]          + egp[jc]          + g_biasc[jc];
        float gg = rgp[2 * HH + jc] + egp[2 * HH + jc] + g_biasc[2 * HH + jc];
        float go = rgp[3 * HH + jc] + egp[3 * HH + jc] + g_biasc[3 * HH + jc];
        float cn = sigf(gi) * tanhf(gg);
        hv[u] = tf32r(sigf(go) * tanhf(cn));   // rounded: GEMM input
        cv[u] = cn;                            // exact
    }
    size_t offp = (size_t)n * HH + j;
    *reinterpret_cast<float4*>(&g_h0[offp]) = h4;
    *reinterpret_cast<float4*>(&g_c[offp])  = c4;
    if (len == 1) *reinterpret_cast<float4*>(&g_pemb[offp]) = h4;
}

// ---------------- LSTM cell (after gates GEMM), permuted layout ------------
__global__ void cell_kernel(const int* __restrict__ rel_idx, const int* __restrict__ ent_idx,
                            const int* __restrict__ path_lens, const int* __restrict__ perm,
                            const int* __restrict__ cntp, int t,
                            const float* __restrict__ gates, float* __restrict__ h_next) {
    int n = blockIdx.x;
    if (n >= __ldg(cntp)) return;
    int orig = perm[n];
    int j = threadIdx.x * 4;
    int ridx = rel_idx[orig * LL + t];
    int eidx = ent_idx[orig * LL + t];
    bool emit = (path_lens[orig] == t + 1);
    const float* gb  = &gates[(size_t)n * G4];
    const float* rgp = &g_rel_gate[(size_t)ridx * G4];
    const float* egp = &g_ent_gate[(size_t)eidx * G4];

    float4 gi4 = ld4(gb + j),          ri4 = ld4(rgp + j),          ei4 = ld4(egp + j),          bi4 = ld4(&g_biasc[j]);
    float4 gf4 = ld4(gb + HH + j),     rf4 = ld4(rgp + HH + j),     ef4 = ld4(egp + HH + j),     bf4 = ld4(&g_biasc[HH + j]);
    float4 gg4 = ld4(gb + 2*HH + j),   rg4 = ld4(rgp + 2*HH + j),   eg4 = ld4(egp + 2*HH + j),   bg4 = ld4(&g_biasc[2*HH + j]);
    float4 go4 = ld4(gb + 3*HH + j),   ro4 = ld4(rgp + 3*HH + j),   eo4 = ld4(egp + 3*HH + j),   bo4 = ld4(&g_biasc[3*HH + j]);
    size_t off = (size_t)n * HH + j;
    float4 cold = ld4(&g_c[off]);

    const float* pgi = &gi4.x; const float* pri = &ri4.x; const float* pei = &ei4.x; const float* pbi = &bi4.x;
    const float* pgf = &gf4.x; const float* prf = &rf4.x; const float* pef = &ef4.x; const float* pbf = &bf4.x;
    const float* pgg = &gg4.x; const float* prg = &rg4.x; const float* peg = &eg4.x; const float* pbg = &bg4.x;
    const float* pgo = &go4.x; const float* pro = &ro4.x; const float* peo = &eo4.x; const float* pbo = &bo4.x;
    const float* pc  = &cold.x;

    float4 hn4, cn4;
    float* ph = &hn4.x;
    float* pcn = &cn4.x;
#pragma unroll
    for (int u = 0; u < 4; u++) {
        float gi = pgi[u] + pri[u] + pei[u] + pbi[u];
        float gf = pgf[u] + prf[u] + pef[u] + pbf[u];
        float gg = pgg[u] + prg[u] + peg[u] + pbg[u];
        float go = pgo[u] + pro[u] + peo[u] + pbo[u];
        float cn = sigf(gf) * pc[u] + sigf(gi) * tanhf(gg);
        pcn[u] = cn;
        ph[u] = tf32r(sigf(go) * tanhf(cn));   // rounded: GEMM input
    }
    *reinterpret_cast<float4*>(&g_c[off]) = cn4;
    *reinterpret_cast<float4*>(&h_next[off]) = hn4;
    if (emit) *reinterpret_cast<float4*>(&g_pemb[off]) = hn4;
}

// qkv rows for len==0 paths: pemb row is zero -> qkv row = bias (orig layout)
__global__ void qkv_fill_kernel(const float* __restrict__ bias,
                                const int* __restrict__ perm, const int* __restrict__ cntp) {
    int m = blockIdx.x;
    if (m < __ldg(cntp)) return;
    int orig = perm[m];
    float4* row = reinterpret_cast<float4*>(&g_qkv[(size_t)orig * (3 * HH)]);
    const float4* b4 = reinterpret_cast<const float4*>(bias);
    for (int i = threadIdx.x; i < (3 * HH) / 4; i += blockDim.x) row[i] = b4[i];
}

// ---------------- per-pair attention; mean over K folded into column-sum ----
__global__ void attn_kernel() {
    int p = blockIdx.x;
    int tid = threadIdx.x;
    __shared__ float sq[KK][128], sk[KK][128], sv[KK][128];
    __shared__ float sc[KK][KK + 2];
    __shared__ float wcol[KK];

    for (int hd = 0; hd < 4; hd++) {
        for (int i = tid; i < KK * 128; i += 256) {
            int a = i >> 7, d = i & 127;
            size_t base = (size_t)(p * KK + a) * (3 * HH) + hd * 128 + d;
            sq[a][d] = g_qkv[base];
            sk[a][d] = g_qkv[base + HH];
            sv[a][d] = g_qkv[base + 2 * HH];
        }
        __syncthreads();
        if (tid < KK * KK) {
            int a = tid / KK, b = tid % KK;
            float s = 0.f;
#pragma unroll 8
            for (int d = 0; d < 128; d++) s += sq[a][d] * sk[b][d];
            sc[a][b] = s * 0.08838834764831845f;
        }
        __syncthreads();
        if (tid < KK) {
            int a = tid;
            float mx = -1e30f;
            for (int b = 0; b < KK; b++) mx = fmaxf(mx, sc[a][b]);
            float e[KK], sum = 0.f;
            for (int b = 0; b < KK; b++) { e[b] = expf(sc[a][b] - mx); sum += e[b]; }
            float inv = 1.f / sum;
            for (int b = 0; b < KK; b++) sc[a][b] = e[b] * inv;
        }
        __syncthreads();
        if (tid < KK) {
            int b = tid;
            float s = 0.f;
            for (int a = 0; a < KK; a++) s += sc[a][b];
            wcol[b] = s * 0.1f;
        }
        __syncthreads();
        if (tid < 128) {
            int d = tid;
            float s = 0.f;
#pragma unroll
            for (int b = 0; b < KK; b++) s += wcol[b] * sv[b][d];
            g_ctxmean[(size_t)p * HH + hd * 128 + d] = tf32r(s);  // rounded: GEMM input
        }
        __syncthreads();
    }
}

// ---------------- launch --------------------------------------------------
extern "C" void kernel_launch(void* const* d_in, const int* in_sizes, int n_in,
                              void* d_out, int out_size) {
    const int*   rel_idx     = (const int*)d_in[0];
    const int*   ent_idx     = (const int*)d_in[1];
    const int*   path_lens   = (const int*)d_in[2];
    const float* rel_table   = (const float*)d_in[3];
    const float* ent_table   = (const float*)d_in[4];
    const float* kg_proj_w   = (const float*)d_in[5];
    const float* kg_proj_b   = (const float*)d_in[6];
    const float* w_ih        = (const float*)d_in[7];
    const float* w_hh        = (const float*)d_in[8];
    const float* b_ih        = (const float*)d_in[9];
    const float* b_hh        = (const float*)d_in[10];
    const float* attn_in_w   = (const float*)d_in[11];
    const float* attn_in_b   = (const float*)d_in[12];
    const float* attn_out_w  = (const float*)d_in[13];
    const float* attn_out_b  = (const float*)d_in[14];
    const float* path_proj_w = (const float*)d_in[15];
    const float* path_proj_b = (const float*)d_in[16];
    float* out = (float*)d_out;

    float *pW1, *pW2, *pRel, *pEnt, *pH0, *pH1, *pPemb, *pQkv, *pCtx, *pWc, *pBc2, *pGates;
    float *pWhr, *pAiw, *pEntr, *pRelr;
    int *pPerm, *pCnt;
    cudaGetSymbolAddress((void**)&pW1, g_W1);
    cudaGetSymbolAddress((void**)&pW2, g_W2);
    cudaGetSymbolAddress((void**)&pRel, g_rel_gate);
    cudaGetSymbolAddress((void**)&pEnt, g_ent_gate);
    cudaGetSymbolAddress((void**)&pH0, g_h0);
    cudaGetSymbolAddress((void**)&pH1, g_h1);
    cudaGetSymbolAddress((void**)&pPemb, g_pemb);
    cudaGetSymbolAddress((void**)&pQkv, g_qkv);
    cudaGetSymbolAddress((void**)&pCtx, g_ctxmean);
    cudaGetSymbolAddress((void**)&pWc, g_Wc);
    cudaGetSymbolAddress((void**)&pBc2, g_bc2);
    cudaGetSymbolAddress((void**)&pGates, g_gates);
    cudaGetSymbolAddress((void**)&pWhr, g_whr);
    cudaGetSymbolAddress((void**)&pAiw, g_aiw);
    cudaGetSymbolAddress((void**)&pEntr, g_entr);
    cudaGetSymbolAddress((void**)&pRelr, g_relr);
    cudaGetSymbolAddress((void**)&pPerm, g_perm);
    cudaGetSymbolAddress((void**)&pCnt, g_cnt);

    cudaFuncSetAttribute(mma_gemm, cudaFuncAttributeMaxDynamicSharedMemorySize, MG_SMEM);

    // 0. counting sort by path length (descending)
    sort_init<<<1, 32>>>();
    sort_count<<<(NPK + 255) / 256, 256>>>(path_lens);
    sort_prefix<<<1, 1>>>();
    sort_scatter<<<(NPK + 255) / 256, 256>>>(path_lens);

    // 0b. tf32-rounded operand copies
    round_tf32_kernel<<<(G4 * HH / 4 + 255) / 256, 256>>>(w_hh, pWhr, G4 * HH / 4);
    round_tf32_kernel<<<(3 * HH * HH / 4 + 255) / 256, 256>>>(attn_in_w, pAiw, 3 * HH * HH / 4);
    round_tf32_kernel<<<(NENT * EE / 4 + 255) / 256, 256>>>(ent_table, pEntr, NENT * EE / 4);
    round_tf32_kernel<<<(NREL * EE / 4 + 255) / 256, 256>>>(rel_table, pRelr, NREL * EE / 4);

    // 1. folded weights + biases (fp32 precompute, outputs rounded where GEMM inputs)
    gemm_nn_small<true><<<dim3(EE / BN, G4 / BM), TPB>>>(w_ih,      kg_proj_w, pW1,
                                                         G4, EE, HH, 2 * HH, EE, EE);
    gemm_nn_small<true><<<dim3(EE / BN, G4 / BM), TPB>>>(w_ih + HH, kg_proj_w, pW2,
                                                         G4, EE, HH, 2 * HH, EE, EE);
    biasc_kernel<<<G4, 128>>>(kg_proj_b, w_ih, b_ih, b_hh);
    gemm_nn_small<true><<<dim3(HH / BN, HH / BM), TPB>>>(path_proj_w, attn_out_w, pWc,
                                                         HH, HH, HH, HH, HH, HH);
    biasfold_kernel<<<HH, 128>>>(path_proj_w, attn_out_b, path_proj_b);

    // 2. per-entity gate tables (tensor cores, tf32)
    mma_gemm<<<dim3(G4 / 128, (NENT + 127) / 128), 256, MG_SMEM>>>(
        pEntr, EE, pW2, nullptr, pEnt, G4, NENT, EE, nullptr, nullptr);
    mma_gemm<<<dim3(G4 / 128, (NREL + 127) / 128), 256, MG_SMEM>>>(
        pRelr, EE, pW1, nullptr, pRel, G4, NREL, EE, nullptr, nullptr);

    // 3. LSTM: step 0 (gather); steps 1,2 = gates GEMM + cell on compacted prefix
    step0_kernel<<<NPK, 128>>>(rel_idx, ent_idx, path_lens, pPerm);
    mma_gemm<<<dim3(G4 / 128, NPK / 128), 256, MG_SMEM>>>(
        pH0, HH, pWhr, nullptr, pGates, G4, NPK, HH, pCnt + 1, nullptr);
    cell_kernel<<<NPK, 128>>>(rel_idx, ent_idx, path_lens, pPerm, pCnt + 1, 1, pGates, pH1);
    mma_gemm<<<dim3(G4 / 128, NPK / 128), 256, MG_SMEM>>>(
        pH1, HH, pWhr, nullptr, pGates, G4, NPK, HH, pCnt + 0, nullptr);
    cell_kernel<<<NPK, 128>>>(rel_idx, ent_idx, path_lens, pPerm, pCnt + 0, 2, pGates, pH0);

    // 4. QKV: tf32 GEMM on compacted permuted pemb rows (A read DIRECTLY),
    //    C scattered to original layout via perm.
    mma_gemm<<<dim3(3 * HH / 128, NPK / 128), 256, MG_SMEM>>>(
        pPemb, HH, pAiw, attn_in_b, pQkv, 3 * HH, NPK, HH, pCnt + 2, pPerm);
    qkv_fill_kernel<<<NPK, 128>>>(attn_in_b, pPerm, pCnt + 2);

    // 5. attention with folded mean
    attn_kernel<<<PP, 256>>>();

    // 6. single folded output projection: out = ctx_mean @ Wc^T + bc2
    mma_gemm<<<dim3(HH / 128, PP / 128), 256, MG_SMEM>>>(
        pCtx, HH, pWc, pBc2, out, HH, PP, HH, nullptr, nullptr);
}